// round 12
// baseline (speedup 1.0000x reference)
#include <cuda_runtime.h>
#include <cuda_fp16.h>
#include <cstdint>

#define BTn 32768
#define Tn  256
#define Cn  384
#define Hn  6
#define Vn  65
#define Fn  1536

// ---------------- scratch (device globals; allocation-free rule) -----------
__device__ __half g_x[BTn*Cn];                      // embeddings fp16
__device__ __half g_bqkvh[128*Cn], g_bqkvl[128*Cn]; // qkv W split [Npad=128,K=384]
__device__ float  g_qkv[BTn*72];                    // qkv activations (f32)
__device__ __half g_att[BTn*64];                    // attn out fp16, Kpad=64
__device__ __half g_bprojh[Cn*64], g_bprojl[Cn*64]; // proj W split [384,Kpad=64]
__device__ __half g_x2[BTn*Cn];                     // proj out fp16
__device__ __half g_b1h[Fn*Cn], g_b1l[Fn*Cn];       // W1^T split [1536,384]
__device__ __half g_h[BTn*Fn];                      // ffn hidden fp16
__device__ __half g_b2h[Cn*Fn], g_b2l[Cn*Fn];       // W2^T split [384,1536]
__device__ __half g_x3[BTn*Cn];                     // ffn out fp16
__device__ __half g_blmh[128*Cn], g_blml[128*Cn];   // Wlm^T split [Npad=128,384]
__device__ float  g_rowloss[BTn];

// ---------------- helpers ----------------------------------------------
__device__ __forceinline__ uint32_t smem_u32(const void* p) {
    return (uint32_t)__cvta_generic_to_shared(p);
}

__device__ __forceinline__ void cp16(uint32_t dst, const void* src) {
    asm volatile("cp.async.cg.shared.global [%0], [%1], 16;" :: "r"(dst), "l"(src));
}
#define CP_COMMIT() asm volatile("cp.async.commit_group;" ::: "memory")
#define CP_WAIT(n)  asm volatile("cp.async.wait_group %0;" :: "n"(n) : "memory")

__device__ __forceinline__ void mma_f16(float* d, const uint32_t* a, uint32_t b0, uint32_t b1) {
    asm volatile(
        "mma.sync.aligned.m16n8k16.row.col.f32.f16.f16.f32 "
        "{%0,%1,%2,%3}, {%4,%5,%6,%7}, {%8,%9}, {%0,%1,%2,%3};"
        : "+f"(d[0]), "+f"(d[1]), "+f"(d[2]), "+f"(d[3])
        : "r"(a[0]), "r"(a[1]), "r"(a[2]), "r"(a[3]), "r"(b0), "r"(b1));
}

__device__ __forceinline__ void ldm_x4(uint32_t* r, uint32_t addr) {
    asm volatile("ldmatrix.sync.aligned.m8n8.x4.shared.b16 {%0,%1,%2,%3}, [%4];"
        : "=r"(r[0]), "=r"(r[1]), "=r"(r[2]), "=r"(r[3]) : "r"(addr));
}

__device__ __forceinline__ void split2h(float v, __half& h, __half& l) {
    h = __float2half_rn(v);
    l = __float2half_rn(v - __half2float(h));
}

// ---------------- fused pack + embed (one launch) ---------------------------
#define S0 (128*Cn)
#define S1 (Cn*64)
#define S2 (Fn*Cn)
#define S3 (Cn*Fn)
#define S4 (128*Cn)
#define PACKT (S0 + S1 + S2 + S3 + S4)

__global__ void pack_embed(const float* __restrict__ Wq, const float* __restrict__ Wk,
                           const float* __restrict__ Wv, const float* __restrict__ Wproj,
                           const float* __restrict__ W1, const float* __restrict__ W2,
                           const float* __restrict__ Wlm,
                           const int* __restrict__ idx, const float* __restrict__ tok,
                           const float* __restrict__ pos) {
    int i = blockIdx.x * blockDim.x + threadIdx.x;
    if (i < PACKT) {
        float v; __half *hi, *lo; int o;
        if (i < S0) {
            o = i; int n = o / Cn, k = o - n * Cn;
            if (n < 72) {
                int g = n / 24, rem = n - g * 24, h = rem >> 2, d = rem & 3;
                const float* W = (g == 0) ? Wq : (g == 1) ? Wk : Wv;
                v = W[(h * Cn + k) * 4 + d];
            } else v = 0.f;
            hi = g_bqkvh; lo = g_bqkvl;
        } else if (i < S0 + S1) {
            o = i - S0; int n = o >> 6, k = o & 63;
            v = (k < 24) ? Wproj[k * Cn + n] : 0.f;
            hi = g_bprojh; lo = g_bprojl;
        } else if (i < S0 + S1 + S2) {
            o = i - S0 - S1; int n = o / Cn, k = o - n * Cn;
            v = W1[(size_t)k * Fn + n];
            hi = g_b1h; lo = g_b1l;
        } else if (i < S0 + S1 + S2 + S3) {
            o = i - S0 - S1 - S2; int n = o / Fn, k = o - n * Fn;
            v = W2[(size_t)k * Cn + n];
            hi = g_b2h; lo = g_b2l;
        } else {
            o = i - S0 - S1 - S2 - S3; int n = o / Cn, k = o - n * Cn;
            v = (n < Vn) ? Wlm[k * Vn + n] : 0.f;
            hi = g_blmh; lo = g_blml;
        }
        __half h, l; split2h(v, h, l);
        hi[o] = h; lo[o] = l;
        return;
    }
    int e = i - PACKT;
    if (e >= BTn * Cn) return;
    int bt = e / Cn, c = e - bt * Cn;
    int t = bt & (Tn - 1);
    g_x[e] = __float2half_rn(tok[__ldg(&idx[bt]) * Cn + c] + pos[t * Cn + c]);
}

// ---------------- fp16 2-product GEMM, BK=64, 64x32 warp tiles --------------
// C[M,N] = A[M,K] @ (Bh+Bl)^T. 128x128 CTA tile, BK=64, 8 warps (2M x 4N),
// warp tile 64x32: A frags reused across h/l passes -> 32 ldm.x4/warp/chunk
// (vs 40 with 32x64), cutting smem crossbar reads 164->128KB per CTA-chunk.
// smem tile: [128 rows][64 fp16] = 128B rows, XOR-8 swizzle on 16B chunks.
// LOSSFUSE: after epilogue, compute per-row NLL from logits (lm kernel only).
#define TILE_B 16384
#define STAGE_B (3 * TILE_B)     // A, Bh, Bl = 49152
#define NSTAGE 2

template <bool RELU, bool HASBIAS, bool HALFOUT, bool LOSSFUSE>
__global__ __launch_bounds__(256, 2) void tc_gemm(
    const __half* __restrict__ A, int Kpad,
    const __half* __restrict__ Bh, const __half* __restrict__ Bl,
    const float* __restrict__ bias,
    float* __restrict__ Cf, int ldc, int Nreal,
    __half* __restrict__ Ch, int Npad,
    const int* __restrict__ targets)
{
    extern __shared__ char smem[];
    const int tid  = threadIdx.x;
    const int lane = tid & 31, wid = tid >> 5;
    const int wm = wid & 1, wn = wid >> 1;       // 2x4 warp grid, 64x32 tiles
    const int m0 = blockIdx.y * 128, n0 = blockIdx.x * 128;

    const __half* gsrc[3] = {
        A  + (size_t)m0 * Kpad,
        Bh + (size_t)n0 * Kpad,
        Bl + (size_t)n0 * Kpad };

    const int nk = Kpad / 64;
    const uint32_t sbase = smem_u32(smem);

    auto load_stage = [&](int stage, int c) {
        uint32_t dst0 = sbase + stage * STAGE_B;
        int kc0 = c * 64;
#pragma unroll
        for (int tile = 0; tile < 3; tile++) {
            const __half* g = gsrc[tile] + kc0;
#pragma unroll
            for (int t = 0; t < 4; t++) {
                int j = tid + t * 256;               // 0..1023
                int row = j >> 3, sx = j & 7;
                uint32_t sw = (uint32_t)(row * 128 + ((sx ^ (row & 7)) << 4));
                cp16(dst0 + tile * TILE_B + sw, g + (size_t)row * Kpad + sx * 8);
            }
        }
        CP_COMMIT();
    };

    float acc[4][4][4];   // [mi m16][nj n8][frag]
#pragma unroll
    for (int mi = 0; mi < 4; mi++)
#pragma unroll
        for (int nj = 0; nj < 4; nj++)
#pragma unroll
            for (int q = 0; q < 4; q++) acc[mi][nj][q] = 0.f;

    load_stage(0, 0);

    // ldmatrix lane addressing (128B rows, XOR-8 swizzle)
    const uint32_t lrow128 = (uint32_t)((lane & 15) * 128);
    const uint32_t xh = (uint32_t)(lane >> 4);
    const uint32_t sxor = (uint32_t)(lane & 7);
    const int r8 = lane >> 2, q4 = lane & 3;

    for (int c = 0; c < nk; c++) {
        CP_WAIT(0);
        __syncthreads();
        if (c + 1 < nk) load_stage((c + 1) & 1, c + 1);

        const uint32_t st = sbase + (uint32_t)((c & 1) * STAGE_B);
        const uint32_t stA  = st + (uint32_t)(wm * 8192) + lrow128;          // 64 rows
        const uint32_t stBh = st + TILE_B     + (uint32_t)(wn * 4096) + lrow128; // 32 cols
        const uint32_t stBl = st + 2 * TILE_B + (uint32_t)(wn * 4096) + lrow128;

#pragma unroll
        for (int ks = 0; ks < 4; ks++) {
            const uint32_t colx = ((2u * (uint32_t)ks + xh) ^ sxor) << 4;
            uint32_t a[4][4];
            ldm_x4(a[0], stA + colx);
            ldm_x4(a[1], stA + colx + 2048);
            ldm_x4(a[2], stA + colx + 4096);
            ldm_x4(a[3], stA + colx + 6144);
            uint32_t b0[4], b1[4];

            // ---- h pass ----
            ldm_x4(b0, stBh + colx);
            ldm_x4(b1, stBh + colx + 2048);
#pragma unroll
            for (int mi = 0; mi < 4; mi++) {
                mma_f16(acc[mi][0], a[mi], b0[0], b0[2]);
                mma_f16(acc[mi][1], a[mi], b0[1], b0[3]);
                mma_f16(acc[mi][2], a[mi], b1[0], b1[2]);
                mma_f16(acc[mi][3], a[mi], b1[1], b1[3]);
            }
            // ---- l pass (A frags reused) ----
            ldm_x4(b0, stBl + colx);
            ldm_x4(b1, stBl + colx + 2048);
#pragma unroll
            for (int mi = 0; mi < 4; mi++) {
                mma_f16(acc[mi][0], a[mi], b0[0], b0[2]);
                mma_f16(acc[mi][1], a[mi], b0[1], b0[3]);
                mma_f16(acc[mi][2], a[mi], b1[0], b1[2]);
                mma_f16(acc[mi][3], a[mi], b1[1], b1[3]);
            }
        }
    }

    if (LOSSFUSE) __syncthreads();   // smem stages reused for logits below

    float* lg = (float*)smem;        // [128][68] when LOSSFUSE

    // ---- epilogue ----
#pragma unroll
    for (int mi = 0; mi < 4; mi++) {
#pragma unroll
        for (int nj = 0; nj < 4; nj++) {
            int colg = n0 + wn * 32 + nj * 8 + q4 * 2;
#pragma unroll
            for (int half = 0; half < 2; half++) {
                int rowg = m0 + wm * 64 + mi * 16 + r8 + half * 8;
                float v0 = acc[mi][nj][half * 2 + 0];
                float v1 = acc[mi][nj][half * 2 + 1];
                if (HASBIAS) { v0 += bias[colg]; v1 += bias[colg + 1]; }
                if (RELU) { v0 = fmaxf(v0, 0.f); v1 = fmaxf(v1, 0.f); }
                if (HALFOUT) {
                    __half2 hp;
                    hp.x = __float2half_rn(v0);
                    hp.y = __float2half_rn(v1);
                    *(__half2*)(Ch + (size_t)rowg * Npad + colg) = hp;
                } else {
                    if (colg < Nreal)     Cf[(size_t)rowg * ldc + colg]     = v0;
                    if (colg + 1 < Nreal) Cf[(size_t)rowg * ldc + colg + 1] = v1;
                    if (LOSSFUSE) {
                        int r = rowg - m0;
                        if (colg < Vn)     lg[r * 68 + colg]     = v0;
                        if (colg + 1 < Vn) lg[r * 68 + colg + 1] = v1;
                    }
                }
            }
        }
    }

    if (LOSSFUSE) {
        __syncthreads();
        for (int r = wid; r < 128; r += 8) {
            const float* row = lg + r * 68;
            float v0 = row[lane];
            float v1 = row[lane + 32];
            float v2 = (lane == 0) ? row[64] : -1e30f;
            float mx = fmaxf(fmaxf(v0, v1), v2);
#pragma unroll
            for (int o = 16; o; o >>= 1) mx = fmaxf(mx, __shfl_xor_sync(0xffffffffu, mx, o));
            float se = __expf(v0 - mx) + __expf(v1 - mx) + ((lane == 0) ? __expf(v2 - mx) : 0.f);
#pragma unroll
            for (int o = 16; o; o >>= 1) se += __shfl_xor_sync(0xffffffffu, se, o);
            if (lane == 0) {
                int rowg = m0 + r;
                int tg = targets[rowg];
                g_rowloss[rowg] = -(row[tg] - mx - __logf(se));
            }
        }
    }
}

// ---------------- attention: block per (b,h), warp per row ------------------
__global__ __launch_bounds__(256) void attn_kernel() {
    int b = blockIdx.x / Hn;
    int h = blockIdx.x - b * Hn;
    int tid = threadIdx.x;
    int w = tid >> 5, lane = tid & 31;

    __shared__ float4 ks[Tn];
    __shared__ float4 vs[Tn];

    {
        int base = (b * Tn + tid) * 72;
        ks[tid] = *(const float4*)&g_qkv[base + 24 + h * 4];
        vs[tid] = *(const float4*)&g_qkv[base + 48 + h * 4];
    }
    __syncthreads();

    const float scale = 0.05103103630798287f;  // 1/sqrt(384)

    for (int t = w; t < Tn; t += 8) {
        float4 q = *(const float4*)&g_qkv[(b * Tn + t) * 72 + h * 4];
        q.x *= scale; q.y *= scale; q.z *= scale; q.w *= scale;
        float l = 0.f, ax = 0.f, ay = 0.f, az = 0.f, aw = 0.f;
        for (int s = lane; s <= t; s += 32) {
            float4 k = ks[s];
            float p = __expf(q.x*k.x + q.y*k.y + q.z*k.z + q.w*k.w);
            float4 v = vs[s];
            l += p;
            ax = fmaf(p, v.x, ax);
            ay = fmaf(p, v.y, ay);
            az = fmaf(p, v.z, az);
            aw = fmaf(p, v.w, aw);
        }
#pragma unroll
        for (int o = 16; o; o >>= 1) {
            l  += __shfl_xor_sync(0xffffffffu, l,  o);
            ax += __shfl_xor_sync(0xffffffffu, ax, o);
            ay += __shfl_xor_sync(0xffffffffu, ay, o);
            az += __shfl_xor_sync(0xffffffffu, az, o);
            aw += __shfl_xor_sync(0xffffffffu, aw, o);
        }
        if (lane == 0) {
            float inv = 1.f / l;
            size_t rb = (size_t)(b * Tn + t) * 64 + h * 4;
            __half2 p0, p1;
            p0.x = __float2half_rn(ax * inv);
            p0.y = __float2half_rn(ay * inv);
            p1.x = __float2half_rn(az * inv);
            p1.y = __float2half_rn(aw * inv);
            *(__half2*)(g_att + rb)     = p0;
            *(__half2*)(g_att + rb + 2) = p1;
        }
    }

    if (h == 0) {
        size_t rb = (size_t)(b * Tn + tid) * 64;
        __half2 z; z.x = __float2half_rn(0.f); z.y = z.x;
#pragma unroll
        for (int c = 24; c < 64; c += 2)
            *(__half2*)(g_att + rb + c) = z;
    }
}

// ---------------- loss reduce ------------------------------------------------
__global__ __launch_bounds__(256) void loss_reduce_kernel(float* __restrict__ out,
                                                          int out_size) {
    __shared__ float sm[256];
    int tid = threadIdx.x;
    float s = 0.f;
    for (int i = tid; i < BTn; i += 256) s += g_rowloss[i];
    sm[tid] = s;
    __syncthreads();
    for (int st = 128; st > 0; st >>= 1) {
        if (tid < st) sm[tid] += sm[tid + st];
        __syncthreads();
    }
    float loss = sm[0] * (1.f / BTn);
    for (int i = BTn * Vn + tid; i < out_size; i += 256) out[i] = loss;
}

// ---------------------------------------------------------------------------
extern "C" void kernel_launch(void* const* d_in, const int* in_sizes, int n_in,
                              void* d_out, int out_size) {
    const int*   idx     = (const int*)d_in[0];
    const int*   targets = (const int*)d_in[1];
    const float* tok     = (const float*)d_in[2];
    const float* pos     = (const float*)d_in[3];
    const float* Wq      = (const float*)d_in[4];
    const float* Wk      = (const float*)d_in[5];
    const float* Wv      = (const float*)d_in[6];
    const float* Wproj   = (const float*)d_in[7];
    const float* bproj   = (const float*)d_in[8];
    const float* W1      = (const float*)d_in[9];
    const float* b1      = (const float*)d_in[10];
    const float* W2      = (const float*)d_in[11];
    const float* b2      = (const float*)d_in[12];
    const float* Wlm     = (const float*)d_in[13];
    const float* blm     = (const float*)d_in[14];
    float* out = (float*)d_out;

    void *px, *pbqh, *pbql, *pqkv, *pat, *pbph, *pbpl;
    void *px2, *pb1h, *pb1l, *ph, *pb2h, *pb2l, *px3, *pblh, *pbll;
    cudaGetSymbolAddress(&px, g_x);
    cudaGetSymbolAddress(&pbqh, g_bqkvh); cudaGetSymbolAddress(&pbql, g_bqkvl);
    cudaGetSymbolAddress(&pqkv, g_qkv);
    cudaGetSymbolAddress(&pat, g_att);
    cudaGetSymbolAddress(&pbph, g_bprojh); cudaGetSymbolAddress(&pbpl, g_bprojl);
    cudaGetSymbolAddress(&px2, g_x2);
    cudaGetSymbolAddress(&pb1h, g_b1h);   cudaGetSymbolAddress(&pb1l, g_b1l);
    cudaGetSymbolAddress(&ph, g_h);
    cudaGetSymbolAddress(&pb2h, g_b2h);   cudaGetSymbolAddress(&pb2l, g_b2l);
    cudaGetSymbolAddress(&px3, g_x3);
    cudaGetSymbolAddress(&pblh, g_blmh);  cudaGetSymbolAddress(&pbll, g_blml);

    const int SMEM = NSTAGE * STAGE_B;  // 98304
    cudaFuncSetAttribute(tc_gemm<false,false,false,false>, cudaFuncAttributeMaxDynamicSharedMemorySize, SMEM);
    cudaFuncSetAttribute(tc_gemm<false,true, true, false>, cudaFuncAttributeMaxDynamicSharedMemorySize, SMEM);
    cudaFuncSetAttribute(tc_gemm<true, true, true, false>, cudaFuncAttributeMaxDynamicSharedMemorySize, SMEM);
    cudaFuncSetAttribute(tc_gemm<false,true, false,true >, cudaFuncAttributeMaxDynamicSharedMemorySize, SMEM);

    {
        const int total = PACKT + BTn * Cn;
        pack_embed<<<(total + 255)/256, 256>>>(Wq, Wk, Wv, Wproj, W1, W2, Wlm,
                                               idx, tok, pos);                  // L1
    }

    // qkv: [BT,384] @ [384,72pad128] -> float g_qkv                            // L2
    tc_gemm<false,false,false,false><<<dim3(1, BTn/128), 256, SMEM>>>(
        (const __half*)px, Cn,
        (const __half*)pbqh, (const __half*)pbql,
        nullptr, (float*)pqkv, 72, 72, nullptr, 0, nullptr);

    attn_kernel<<<128 * Hn, 256>>>();                                           // L3

    // proj: [BT,64pad] @ [64,384] + bproj -> fp16 x2                           // L4
    tc_gemm<false,true,true,false><<<dim3(3, BTn/128), 256, SMEM>>>(
        (const __half*)pat, 64,
        (const __half*)pbph, (const __half*)pbpl,
        bproj, nullptr, 0, 0, (__half*)px2, Cn, nullptr);

    // ffn1: relu([BT,384] @ [384,1536] + b1) -> fp16 h
    tc_gemm<true,true,true,false><<<dim3(12, BTn/128), 256, SMEM>>>(
        (const __half*)px2, Cn,
        (const __half*)pb1h, (const __half*)pb1l,
        b1, nullptr, 0, 0, (__half*)ph, Fn, nullptr);

    // ffn2: [BT,1536] @ [1536,384] + b2 -> fp16 x3
    tc_gemm<false,true,true,false><<<dim3(3, BTn/128), 256, SMEM>>>(
        (const __half*)ph, Fn,
        (const __half*)pb2h, (const __half*)pb2l,
        b2, nullptr, 0, 0, (__half*)px3, Cn, nullptr);

    // lm: [BT,384] @ [384,65pad128] + blm -> logits into out + fused rowloss
    tc_gemm<false,true,false,true><<<dim3(1, BTn/128), 256, SMEM>>>(
        (const __half*)px3, Cn,
        (const __half*)pblh, (const __half*)pbll,
        blm, out, Vn, Vn, nullptr, 0, targets);

    loss_reduce_kernel<<<1, 256>>>(out, out_size);
}

// round 13
// speedup vs baseline: 1.0552x; 1.0552x over previous
#include <cuda_runtime.h>
#include <cuda_fp16.h>
#include <cstdint>

#define BTn 32768
#define Tn  256
#define Cn  384
#define Hn  6
#define Vn  65
#define Fn  1536

// ---------------- scratch (device globals; allocation-free rule) -----------
__device__ __half g_x[BTn*Cn];                      // embeddings fp16
__device__ __half g_bqkvh[128*Cn], g_bqkvl[128*Cn]; // qkv W split [Npad=128,K=384]
__device__ float  g_qkv[BTn*72];                    // qkv activations (f32)
__device__ __half g_att[BTn*64];                    // attn out fp16, Kpad=64
__device__ __half g_bprojh[Cn*64], g_bprojl[Cn*64]; // proj W split [384,Kpad=64]
__device__ __half g_x2[BTn*Cn];                     // proj out fp16
__device__ __half g_b1h[Fn*Cn], g_b1l[Fn*Cn];       // W1^T split [1536,384]
__device__ __half g_h[BTn*Fn];                      // ffn hidden fp16
__device__ __half g_b2h[Cn*Fn], g_b2l[Cn*Fn];       // W2^T split [384,1536]
__device__ __half g_x3[BTn*Cn];                     // ffn out fp16
__device__ __half g_blmh[128*Cn], g_blml[128*Cn];   // Wlm^T split [Npad=128,384]
__device__ float  g_rowloss[BTn];

// ---------------- helpers ----------------------------------------------
__device__ __forceinline__ uint32_t smem_u32(const void* p) {
    return (uint32_t)__cvta_generic_to_shared(p);
}

__device__ __forceinline__ void cp16(uint32_t dst, const void* src) {
    asm volatile("cp.async.cg.shared.global [%0], [%1], 16;" :: "r"(dst), "l"(src));
}
#define CP_COMMIT() asm volatile("cp.async.commit_group;" ::: "memory")
#define CP_WAIT(n)  asm volatile("cp.async.wait_group %0;" :: "n"(n) : "memory")

__device__ __forceinline__ void mma_f16(float* d, const uint32_t* a, uint32_t b0, uint32_t b1) {
    asm volatile(
        "mma.sync.aligned.m16n8k16.row.col.f32.f16.f16.f32 "
        "{%0,%1,%2,%3}, {%4,%5,%6,%7}, {%8,%9}, {%0,%1,%2,%3};"
        : "+f"(d[0]), "+f"(d[1]), "+f"(d[2]), "+f"(d[3])
        : "r"(a[0]), "r"(a[1]), "r"(a[2]), "r"(a[3]), "r"(b0), "r"(b1));
}

__device__ __forceinline__ void ldm_x4(uint32_t* r, uint32_t addr) {
    asm volatile("ldmatrix.sync.aligned.m8n8.x4.shared.b16 {%0,%1,%2,%3}, [%4];"
        : "=r"(r[0]), "=r"(r[1]), "=r"(r[2]), "=r"(r[3]) : "r"(addr));
}

__device__ __forceinline__ void split2h(float v, __half& h, __half& l) {
    h = __float2half_rn(v);
    l = __float2half_rn(v - __half2float(h));
}

// ---------------- fused pack + embed (one launch) ---------------------------
#define S0 (128*Cn)
#define S1 (Cn*64)
#define S2 (Fn*Cn)
#define S3 (Cn*Fn)
#define S4 (128*Cn)
#define PACKT (S0 + S1 + S2 + S3 + S4)

__global__ void pack_embed(const float* __restrict__ Wq, const float* __restrict__ Wk,
                           const float* __restrict__ Wv, const float* __restrict__ Wproj,
                           const float* __restrict__ W1, const float* __restrict__ W2,
                           const float* __restrict__ Wlm,
                           const int* __restrict__ idx, const float* __restrict__ tok,
                           const float* __restrict__ pos) {
    int i = blockIdx.x * blockDim.x + threadIdx.x;
    if (i < PACKT) {
        float v; __half *hi, *lo; int o;
        if (i < S0) {
            o = i; int n = o / Cn, k = o - n * Cn;
            if (n < 72) {
                int g = n / 24, rem = n - g * 24, h = rem >> 2, d = rem & 3;
                const float* W = (g == 0) ? Wq : (g == 1) ? Wk : Wv;
                v = W[(h * Cn + k) * 4 + d];
            } else v = 0.f;
            hi = g_bqkvh; lo = g_bqkvl;
        } else if (i < S0 + S1) {
            o = i - S0; int n = o >> 6, k = o & 63;
            v = (k < 24) ? Wproj[k * Cn + n] : 0.f;
            hi = g_bprojh; lo = g_bprojl;
        } else if (i < S0 + S1 + S2) {
            o = i - S0 - S1; int n = o / Cn, k = o - n * Cn;
            v = W1[(size_t)k * Fn + n];
            hi = g_b1h; lo = g_b1l;
        } else if (i < S0 + S1 + S2 + S3) {
            o = i - S0 - S1 - S2; int n = o / Fn, k = o - n * Fn;
            v = W2[(size_t)k * Cn + n];
            hi = g_b2h; lo = g_b2l;
        } else {
            o = i - S0 - S1 - S2 - S3; int n = o / Cn, k = o - n * Cn;
            v = (n < Vn) ? Wlm[k * Vn + n] : 0.f;
            hi = g_blmh; lo = g_blml;
        }
        __half h, l; split2h(v, h, l);
        hi[o] = h; lo[o] = l;
        return;
    }
    int e = i - PACKT;
    if (e >= BTn * Cn) return;
    int bt = e / Cn, c = e - bt * Cn;
    int t = bt & (Tn - 1);
    g_x[e] = __float2half_rn(tok[__ldg(&idx[bt]) * Cn + c] + pos[t * Cn + c]);
}

// ---------------- fp16 2-product GEMM, BK=64, 2-stage (R10 winner) ----------
// C[M,N] = A[M,K] @ (Bh+Bl)^T. 128x128 CTA tile, BK=64, 8 warps (4M x 2N),
// warp tile 32x64. One CP_WAIT + one barrier per 64-K chunk.
// smem tile: [128 rows][64 fp16] = 128B rows, XOR-8 swizzle on 16B chunks.
// LOSSFUSE: after epilogue, compute per-row NLL from logits (lm kernel only).
#define TILE_B 16384
#define STAGE_B (3 * TILE_B)     // A, Bh, Bl = 49152
#define NSTAGE 2

template <bool RELU, bool HASBIAS, bool HALFOUT, bool LOSSFUSE>
__global__ __launch_bounds__(256, 2) void tc_gemm(
    const __half* __restrict__ A, int Kpad,
    const __half* __restrict__ Bh, const __half* __restrict__ Bl,
    const float* __restrict__ bias,
    float* __restrict__ Cf, int ldc, int Nreal,
    __half* __restrict__ Ch, int Npad,
    const int* __restrict__ targets)
{
    extern __shared__ char smem[];
    const int tid  = threadIdx.x;
    const int lane = tid & 31, wid = tid >> 5;
    const int wm = wid & 3, wn = wid >> 2;       // 4x2 warp grid, 32x64 tiles
    const int m0 = blockIdx.y * 128, n0 = blockIdx.x * 128;

    const __half* gsrc[3] = {
        A  + (size_t)m0 * Kpad,
        Bh + (size_t)n0 * Kpad,
        Bl + (size_t)n0 * Kpad };

    const int nk = Kpad / 64;
    const uint32_t sbase = smem_u32(smem);

    auto load_stage = [&](int stage, int c) {
        uint32_t dst0 = sbase + stage * STAGE_B;
        int kc0 = c * 64;
#pragma unroll
        for (int tile = 0; tile < 3; tile++) {
            const __half* g = gsrc[tile] + kc0;
#pragma unroll
            for (int t = 0; t < 4; t++) {
                int j = tid + t * 256;               // 0..1023
                int row = j >> 3, sx = j & 7;
                uint32_t sw = (uint32_t)(row * 128 + ((sx ^ (row & 7)) << 4));
                cp16(dst0 + tile * TILE_B + sw, g + (size_t)row * Kpad + sx * 8);
            }
        }
        CP_COMMIT();
    };

    float acc[2][8][4];
#pragma unroll
    for (int mi = 0; mi < 2; mi++)
#pragma unroll
        for (int nj = 0; nj < 8; nj++)
#pragma unroll
            for (int q = 0; q < 4; q++) acc[mi][nj][q] = 0.f;

    load_stage(0, 0);

    // ldmatrix lane addressing (128B rows, XOR-8 swizzle)
    const uint32_t lrow = (uint32_t)(lane & 15);
    const uint32_t lrow128 = lrow * 128;
    const uint32_t xh = (uint32_t)(lane >> 4);
    const uint32_t sxor = lrow & 7;
    const int r8 = lane >> 2, q4 = lane & 3;

    for (int c = 0; c < nk; c++) {
        CP_WAIT(0);
        __syncthreads();
        if (c + 1 < nk) load_stage((c + 1) & 1, c + 1);

        const uint32_t st = sbase + (uint32_t)((c & 1) * STAGE_B);
        const uint32_t stA  = st + (uint32_t)(wm * 4096) + lrow128;
        const uint32_t stBh = st + TILE_B     + (uint32_t)(wn * 8192) + lrow128;
        const uint32_t stBl = st + 2 * TILE_B + (uint32_t)(wn * 8192) + lrow128;

#pragma unroll
        for (int ks = 0; ks < 4; ks++) {
            const uint32_t colx = ((2u * (uint32_t)ks + xh) ^ sxor) << 4;
            uint32_t a0[4], a1[4];
            ldm_x4(a0, stA + colx);
            ldm_x4(a1, stA + colx + 2048);
            uint32_t b[2][4];

            // ---- h pass: 16 independent HMMAs, B n16-frags double-buffered
            ldm_x4(b[0], stBh + colx);
#pragma unroll
            for (int p = 0; p < 4; p++) {
                const int cur = p & 1;
                if (p < 3) ldm_x4(b[cur ^ 1], stBh + colx + (uint32_t)((p + 1) * 2048));
                mma_f16(acc[0][2*p],   a0, b[cur][0], b[cur][2]);
                mma_f16(acc[0][2*p+1], a0, b[cur][1], b[cur][3]);
                mma_f16(acc[1][2*p],   a1, b[cur][0], b[cur][2]);
                mma_f16(acc[1][2*p+1], a1, b[cur][1], b[cur][3]);
            }
            // ---- l pass ----
            ldm_x4(b[0], stBl + colx);
#pragma unroll
            for (int p = 0; p < 4; p++) {
                const int cur = p & 1;
                if (p < 3) ldm_x4(b[cur ^ 1], stBl + colx + (uint32_t)((p + 1) * 2048));
                mma_f16(acc[0][2*p],   a0, b[cur][0], b[cur][2]);
                mma_f16(acc[0][2*p+1], a0, b[cur][1], b[cur][3]);
                mma_f16(acc[1][2*p],   a1, b[cur][0], b[cur][2]);
                mma_f16(acc[1][2*p+1], a1, b[cur][1], b[cur][3]);
            }
        }
    }

    if (LOSSFUSE) __syncthreads();   // smem stages reused for logits below

    float* lg = (float*)smem;        // [128][68] when LOSSFUSE

    // ---- epilogue ----
#pragma unroll
    for (int mi = 0; mi < 2; mi++) {
#pragma unroll
        for (int nj = 0; nj < 8; nj++) {
            int colg = n0 + wn * 64 + nj * 8 + q4 * 2;
#pragma unroll
            for (int half = 0; half < 2; half++) {
                int rowg = m0 + wm * 32 + mi * 16 + r8 + half * 8;
                float v0 = acc[mi][nj][half * 2 + 0];
                float v1 = acc[mi][nj][half * 2 + 1];
                if (HASBIAS) { v0 += bias[colg]; v1 += bias[colg + 1]; }
                if (RELU) { v0 = fmaxf(v0, 0.f); v1 = fmaxf(v1, 0.f); }
                if (HALFOUT) {
                    __half2 hp;
                    hp.x = __float2half_rn(v0);
                    hp.y = __float2half_rn(v1);
                    *(__half2*)(Ch + (size_t)rowg * Npad + colg) = hp;
                } else {
                    if (colg < Nreal)     Cf[(size_t)rowg * ldc + colg]     = v0;
                    if (colg + 1 < Nreal) Cf[(size_t)rowg * ldc + colg + 1] = v1;
                    if (LOSSFUSE) {
                        int r = rowg - m0;
                        if (colg < Vn)     lg[r * 68 + colg]     = v0;
                        if (colg + 1 < Vn) lg[r * 68 + colg + 1] = v1;
                    }
                }
            }
        }
    }

    if (LOSSFUSE) {
        __syncthreads();
        for (int r = wid; r < 128; r += 8) {
            const float* row = lg + r * 68;
            float v0 = row[lane];
            float v1 = row[lane + 32];
            float v2 = (lane == 0) ? row[64] : -1e30f;
            float mx = fmaxf(fmaxf(v0, v1), v2);
#pragma unroll
            for (int o = 16; o; o >>= 1) mx = fmaxf(mx, __shfl_xor_sync(0xffffffffu, mx, o));
            float se = __expf(v0 - mx) + __expf(v1 - mx) + ((lane == 0) ? __expf(v2 - mx) : 0.f);
#pragma unroll
            for (int o = 16; o; o >>= 1) se += __shfl_xor_sync(0xffffffffu, se, o);
            if (lane == 0) {
                int rowg = m0 + r;
                int tg = targets[rowg];
                g_rowloss[rowg] = -(row[tg] - mx - __logf(se));
            }
        }
    }
}

// ---------------- attention: block per (b,h), warp per row ------------------
__global__ __launch_bounds__(256) void attn_kernel() {
    int b = blockIdx.x / Hn;
    int h = blockIdx.x - b * Hn;
    int tid = threadIdx.x;
    int w = tid >> 5, lane = tid & 31;

    __shared__ float4 ks[Tn];
    __shared__ float4 vs[Tn];

    {
        int base = (b * Tn + tid) * 72;
        ks[tid] = *(const float4*)&g_qkv[base + 24 + h * 4];
        vs[tid] = *(const float4*)&g_qkv[base + 48 + h * 4];
    }
    __syncthreads();

    const float scale = 0.05103103630798287f;  // 1/sqrt(384)

    for (int t = w; t < Tn; t += 8) {
        float4 q = *(const float4*)&g_qkv[(b * Tn + t) * 72 + h * 4];
        q.x *= scale; q.y *= scale; q.z *= scale; q.w *= scale;
        float l = 0.f, ax = 0.f, ay = 0.f, az = 0.f, aw = 0.f;
        for (int s = lane; s <= t; s += 32) {
            float4 k = ks[s];
            float p = __expf(q.x*k.x + q.y*k.y + q.z*k.z + q.w*k.w);
            float4 v = vs[s];
            l += p;
            ax = fmaf(p, v.x, ax);
            ay = fmaf(p, v.y, ay);
            az = fmaf(p, v.z, az);
            aw = fmaf(p, v.w, aw);
        }
#pragma unroll
        for (int o = 16; o; o >>= 1) {
            l  += __shfl_xor_sync(0xffffffffu, l,  o);
            ax += __shfl_xor_sync(0xffffffffu, ax, o);
            ay += __shfl_xor_sync(0xffffffffu, ay, o);
            az += __shfl_xor_sync(0xffffffffu, az, o);
            aw += __shfl_xor_sync(0xffffffffu, aw, o);
        }
        if (lane == 0) {
            float inv = 1.f / l;
            size_t rb = (size_t)(b * Tn + t) * 64 + h * 4;
            __half2 p0, p1;
            p0.x = __float2half_rn(ax * inv);
            p0.y = __float2half_rn(ay * inv);
            p1.x = __float2half_rn(az * inv);
            p1.y = __float2half_rn(aw * inv);
            *(__half2*)(g_att + rb)     = p0;
            *(__half2*)(g_att + rb + 2) = p1;
        }
    }

    if (h == 0) {
        size_t rb = (size_t)(b * Tn + tid) * 64;
        __half2 z; z.x = __float2half_rn(0.f); z.y = z.x;
#pragma unroll
        for (int c = 24; c < 64; c += 2)
            *(__half2*)(g_att + rb + c) = z;
    }
}

// ---------------- loss reduce ------------------------------------------------
__global__ __launch_bounds__(256) void loss_reduce_kernel(float* __restrict__ out,
                                                          int out_size) {
    __shared__ float sm[256];
    int tid = threadIdx.x;
    float s = 0.f;
    for (int i = tid; i < BTn; i += 256) s += g_rowloss[i];
    sm[tid] = s;
    __syncthreads();
    for (int st = 128; st > 0; st >>= 1) {
        if (tid < st) sm[tid] += sm[tid + st];
        __syncthreads();
    }
    float loss = sm[0] * (1.f / BTn);
    for (int i = BTn * Vn + tid; i < out_size; i += 256) out[i] = loss;
}

// ---------------------------------------------------------------------------
extern "C" void kernel_launch(void* const* d_in, const int* in_sizes, int n_in,
                              void* d_out, int out_size) {
    const int*   idx     = (const int*)d_in[0];
    const int*   targets = (const int*)d_in[1];
    const float* tok     = (const float*)d_in[2];
    const float* pos     = (const float*)d_in[3];
    const float* Wq      = (const float*)d_in[4];
    const float* Wk      = (const float*)d_in[5];
    const float* Wv      = (const float*)d_in[6];
    const float* Wproj   = (const float*)d_in[7];
    const float* bproj   = (const float*)d_in[8];
    const float* W1      = (const float*)d_in[9];
    const float* b1      = (const float*)d_in[10];
    const float* W2      = (const float*)d_in[11];
    const float* b2      = (const float*)d_in[12];
    const float* Wlm     = (const float*)d_in[13];
    const float* blm     = (const float*)d_in[14];
    float* out = (float*)d_out;

    void *px, *pbqh, *pbql, *pqkv, *pat, *pbph, *pbpl;
    void *px2, *pb1h, *pb1l, *ph, *pb2h, *pb2l, *px3, *pblh, *pbll;
    cudaGetSymbolAddress(&px, g_x);
    cudaGetSymbolAddress(&pbqh, g_bqkvh); cudaGetSymbolAddress(&pbql, g_bqkvl);
    cudaGetSymbolAddress(&pqkv, g_qkv);
    cudaGetSymbolAddress(&pat, g_att);
    cudaGetSymbolAddress(&pbph, g_bprojh); cudaGetSymbolAddress(&pbpl, g_bprojl);
    cudaGetSymbolAddress(&px2, g_x2);
    cudaGetSymbolAddress(&pb1h, g_b1h);   cudaGetSymbolAddress(&pb1l, g_b1l);
    cudaGetSymbolAddress(&ph, g_h);
    cudaGetSymbolAddress(&pb2h, g_b2h);   cudaGetSymbolAddress(&pb2l, g_b2l);
    cudaGetSymbolAddress(&px3, g_x3);
    cudaGetSymbolAddress(&pblh, g_blmh);  cudaGetSymbolAddress(&pbll, g_blml);

    const int SMEM = NSTAGE * STAGE_B;  // 98304
    cudaFuncSetAttribute(tc_gemm<false,false,false,false>, cudaFuncAttributeMaxDynamicSharedMemorySize, SMEM);
    cudaFuncSetAttribute(tc_gemm<false,true, true, false>, cudaFuncAttributeMaxDynamicSharedMemorySize, SMEM);
    cudaFuncSetAttribute(tc_gemm<true, true, true, false>, cudaFuncAttributeMaxDynamicSharedMemorySize, SMEM);
    cudaFuncSetAttribute(tc_gemm<false,true, false,true >, cudaFuncAttributeMaxDynamicSharedMemorySize, SMEM);

    {
        const int total = PACKT + BTn * Cn;
        pack_embed<<<(total + 255)/256, 256>>>(Wq, Wk, Wv, Wproj, W1, W2, Wlm,
                                               idx, tok, pos);                  // L1
    }

    // qkv: [BT,384] @ [384,72pad128] -> float g_qkv                            // L2
    tc_gemm<false,false,false,false><<<dim3(1, BTn/128), 256, SMEM>>>(
        (const __half*)px, Cn,
        (const __half*)pbqh, (const __half*)pbql,
        nullptr, (float*)pqkv, 72, 72, nullptr, 0, nullptr);

    attn_kernel<<<128 * Hn, 256>>>();                                           // L3

    // proj: [BT,64pad] @ [64,384] + bproj -> fp16 x2                           // L4
    tc_gemm<false,true,true,false><<<dim3(3, BTn/128), 256, SMEM>>>(
        (const __half*)pat, 64,
        (const __half*)pbph, (const __half*)pbpl,
        bproj, nullptr, 0, 0, (__half*)px2, Cn, nullptr);

    // ffn1: relu([BT,384] @ [384,1536] + b1) -> fp16 h
    tc_gemm<true,true,true,false><<<dim3(12, BTn/128), 256, SMEM>>>(
        (const __half*)px2, Cn,
        (const __half*)pb1h, (const __half*)pb1l,
        b1, nullptr, 0, 0, (__half*)ph, Fn, nullptr);

    // ffn2: [BT,1536] @ [1536,384] + b2 -> fp16 x3
    tc_gemm<false,true,true,false><<<dim3(3, BTn/128), 256, SMEM>>>(
        (const __half*)ph, Fn,
        (const __half*)pb2h, (const __half*)pb2l,
        b2, nullptr, 0, 0, (__half*)px3, Cn, nullptr);

    // lm: [BT,384] @ [384,65pad128] + blm -> logits into out + fused rowloss
    tc_gemm<false,true,false,true><<<dim3(1, BTn/128), 256, SMEM>>>(
        (const __half*)px3, Cn,
        (const __half*)pblh, (const __half*)pbll,
        blm, out, Vn, Vn, nullptr, 0, targets);

    loss_reduce_kernel<<<1, 256>>>(out, out_size);
}

// round 14
// speedup vs baseline: 1.4565x; 1.3802x over previous
#include <cuda_runtime.h>
#include <cuda_fp16.h>
#include <cstdint>

#define BTn 32768
#define Tn  256
#define Cn  384
#define Hn  6
#define Vn  65
#define Fn  1536

// ---------------- scratch (device globals; allocation-free rule) -----------
__device__ __half g_x[BTn*Cn];                      // embeddings fp16
__device__ __half g_bqkvh[128*Cn], g_bqkvl[128*Cn]; // qkv W split [Npad=128,K=384]
__device__ float  g_qkv[BTn*72];                    // qkv activations (f32)
__device__ __half g_att[BTn*64];                    // attn out fp16, Kpad=64
__device__ __half g_bprojh[Cn*64], g_bprojl[Cn*64]; // proj W split [384,Kpad=64]
__device__ __half g_x2[BTn*Cn];                     // proj out fp16
__device__ __half g_b1h[Fn*Cn];                     // W1^T fp16 [1536,384]
__device__ __half g_h[BTn*Fn];                      // ffn hidden fp16
__device__ __half g_b2h[Cn*Fn];                     // W2^T fp16 [384,1536]
__device__ __half g_x3[BTn*Cn];                     // ffn out fp16
__device__ __half g_blmh[128*Cn], g_blml[128*Cn];   // Wlm^T split [Npad=128,384]
__device__ float  g_rowloss[BTn];

// ---------------- helpers ----------------------------------------------
__device__ __forceinline__ uint32_t smem_u32(const void* p) {
    return (uint32_t)__cvta_generic_to_shared(p);
}

__device__ __forceinline__ void cp16(uint32_t dst, const void* src) {
    asm volatile("cp.async.cg.shared.global [%0], [%1], 16;" :: "r"(dst), "l"(src));
}
#define CP_COMMIT() asm volatile("cp.async.commit_group;" ::: "memory")
#define CP_WAIT(n)  asm volatile("cp.async.wait_group %0;" :: "n"(n) : "memory")

__device__ __forceinline__ void mma_f16(float* d, const uint32_t* a, uint32_t b0, uint32_t b1) {
    asm volatile(
        "mma.sync.aligned.m16n8k16.row.col.f32.f16.f16.f32 "
        "{%0,%1,%2,%3}, {%4,%5,%6,%7}, {%8,%9}, {%0,%1,%2,%3};"
        : "+f"(d[0]), "+f"(d[1]), "+f"(d[2]), "+f"(d[3])
        : "r"(a[0]), "r"(a[1]), "r"(a[2]), "r"(a[3]), "r"(b0), "r"(b1));
}

__device__ __forceinline__ void ldm_x4(uint32_t* r, uint32_t addr) {
    asm volatile("ldmatrix.sync.aligned.m8n8.x4.shared.b16 {%0,%1,%2,%3}, [%4];"
        : "=r"(r[0]), "=r"(r[1]), "=r"(r[2]), "=r"(r[3]) : "r"(addr));
}

__device__ __forceinline__ void split2h(float v, __half& h, __half& l) {
    h = __float2half_rn(v);
    l = __float2half_rn(v - __half2float(h));
}

// ---------------- fused pack + embed (one launch) ---------------------------
#define S0 (128*Cn)
#define S1 (Cn*64)
#define S2 (Fn*Cn)
#define S3 (Cn*Fn)
#define S4 (128*Cn)
#define PACKT (S0 + S1 + S2 + S3 + S4)

__global__ void pack_embed(const float* __restrict__ Wq, const float* __restrict__ Wk,
                           const float* __restrict__ Wv, const float* __restrict__ Wproj,
                           const float* __restrict__ W1, const float* __restrict__ W2,
                           const float* __restrict__ Wlm,
                           const int* __restrict__ idx, const float* __restrict__ tok,
                           const float* __restrict__ pos) {
    int i = blockIdx.x * blockDim.x + threadIdx.x;
    if (i < PACKT) {
        if (i < S0) {
            int o = i, n = o / Cn, k = o - n * Cn;
            float v = 0.f;
            if (n < 72) {
                int g = n / 24, rem = n - g * 24, h = rem >> 2, d = rem & 3;
                const float* W = (g == 0) ? Wq : (g == 1) ? Wk : Wv;
                v = W[(h * Cn + k) * 4 + d];
            }
            __half h2, l2; split2h(v, h2, l2);
            g_bqkvh[o] = h2; g_bqkvl[o] = l2;
        } else if (i < S0 + S1) {
            int o = i - S0, n = o >> 6, k = o & 63;
            float v = (k < 24) ? Wproj[k * Cn + n] : 0.f;
            __half h2, l2; split2h(v, h2, l2);
            g_bprojh[o] = h2; g_bprojl[o] = l2;
        } else if (i < S0 + S1 + S2) {
            int o = i - S0 - S1, n = o / Cn, k = o - n * Cn;
            g_b1h[o] = __float2half_rn(W1[(size_t)k * Fn + n]);   // single fp16
        } else if (i < S0 + S1 + S2 + S3) {
            int o = i - S0 - S1 - S2, n = o / Fn, k = o - n * Fn;
            g_b2h[o] = __float2half_rn(W2[(size_t)k * Cn + n]);   // single fp16
        } else {
            int o = i - S0 - S1 - S2 - S3, n = o / Cn, k = o - n * Cn;
            float v = (n < Vn) ? Wlm[k * Vn + n] : 0.f;
            __half h2, l2; split2h(v, h2, l2);
            g_blmh[o] = h2; g_blml[o] = l2;
        }
        return;
    }
    int e = i - PACKT;
    if (e >= BTn * Cn) return;
    int bt = e / Cn, c = e - bt * Cn;
    int t = bt & (Tn - 1);
    g_x[e] = __float2half_rn(tok[__ldg(&idx[bt]) * Cn + c] + pos[t * Cn + c]);
}

// ---------------- fp16 GEMM, BK=64, 2-stage (R10 structure) -----------------
// C[M,N] = A[M,K] @ (Bh [+ Bl])^T. 128x128 CTA tile, BK=64, 8 warps (4M x 2N),
// warp tile 32x64. TWOPROD: split-fp16 weights (2 MMA products); else plain
// fp16 weights (1 product, 2 stage tiles instead of 3, no l pass).
// smem tile: [128 rows][64 fp16] = 128B rows, XOR-8 swizzle on 16B chunks.
// LOSSFUSE: after epilogue, compute per-row NLL from logits (lm kernel only).
#define TILE_B 16384
#define NSTAGE 2

template <bool RELU, bool HASBIAS, bool HALFOUT, bool LOSSFUSE, bool TWOPROD>
__global__ __launch_bounds__(256, 2) void tc_gemm(
    const __half* __restrict__ A, int Kpad,
    const __half* __restrict__ Bh, const __half* __restrict__ Bl,
    const float* __restrict__ bias,
    float* __restrict__ Cf, int ldc, int Nreal,
    __half* __restrict__ Ch, int Npad,
    const int* __restrict__ targets)
{
    constexpr uint32_t NT  = TWOPROD ? 3u : 2u;
    constexpr uint32_t STB = NT * TILE_B;

    extern __shared__ char smem[];
    const int tid  = threadIdx.x;
    const int lane = tid & 31, wid = tid >> 5;
    const int wm = wid & 3, wn = wid >> 2;       // 4x2 warp grid, 32x64 tiles
    const int m0 = blockIdx.y * 128, n0 = blockIdx.x * 128;

    const __half* gsrc[3] = {
        A  + (size_t)m0 * Kpad,
        Bh + (size_t)n0 * Kpad,
        TWOPROD ? (Bl + (size_t)n0 * Kpad) : (Bh + (size_t)n0 * Kpad) };

    const int nk = Kpad / 64;
    const uint32_t sbase = smem_u32(smem);

    auto load_stage = [&](int stage, int c) {
        uint32_t dst0 = sbase + stage * STB;
        int kc0 = c * 64;
#pragma unroll
        for (uint32_t tile = 0; tile < NT; tile++) {
            const __half* g = gsrc[tile] + kc0;
#pragma unroll
            for (int t = 0; t < 4; t++) {
                int j = tid + t * 256;               // 0..1023
                int row = j >> 3, sx = j & 7;
                uint32_t sw = (uint32_t)(row * 128 + ((sx ^ (row & 7)) << 4));
                cp16(dst0 + tile * TILE_B + sw, g + (size_t)row * Kpad + sx * 8);
            }
        }
        CP_COMMIT();
    };

    float acc[2][8][4];
#pragma unroll
    for (int mi = 0; mi < 2; mi++)
#pragma unroll
        for (int nj = 0; nj < 8; nj++)
#pragma unroll
            for (int q = 0; q < 4; q++) acc[mi][nj][q] = 0.f;

    load_stage(0, 0);

    // ldmatrix lane addressing (128B rows, XOR-8 swizzle)
    const uint32_t lrow = (uint32_t)(lane & 15);
    const uint32_t lrow128 = lrow * 128;
    const uint32_t xh = (uint32_t)(lane >> 4);
    const uint32_t sxor = lrow & 7;
    const int r8 = lane >> 2, q4 = lane & 3;

    for (int c = 0; c < nk; c++) {
        CP_WAIT(0);
        __syncthreads();
        if (c + 1 < nk) load_stage((c + 1) & 1, c + 1);

        const uint32_t st = sbase + (uint32_t)((c & 1) * STB);
        const uint32_t stA  = st + (uint32_t)(wm * 4096) + lrow128;
        const uint32_t stBh = st + TILE_B     + (uint32_t)(wn * 8192) + lrow128;
        const uint32_t stBl = st + 2 * TILE_B + (uint32_t)(wn * 8192) + lrow128;

#pragma unroll
        for (int ks = 0; ks < 4; ks++) {
            const uint32_t colx = ((2u * (uint32_t)ks + xh) ^ sxor) << 4;
            uint32_t a0[4], a1[4];
            ldm_x4(a0, stA + colx);
            ldm_x4(a1, stA + colx + 2048);
            uint32_t b[2][4];

            // ---- h pass: 16 independent HMMAs, B n16-frags double-buffered
            ldm_x4(b[0], stBh + colx);
#pragma unroll
            for (int p = 0; p < 4; p++) {
                const int cur = p & 1;
                if (p < 3) ldm_x4(b[cur ^ 1], stBh + colx + (uint32_t)((p + 1) * 2048));
                mma_f16(acc[0][2*p],   a0, b[cur][0], b[cur][2]);
                mma_f16(acc[0][2*p+1], a0, b[cur][1], b[cur][3]);
                mma_f16(acc[1][2*p],   a1, b[cur][0], b[cur][2]);
                mma_f16(acc[1][2*p+1], a1, b[cur][1], b[cur][3]);
            }
            if (TWOPROD) {
                // ---- l pass ----
                ldm_x4(b[0], stBl + colx);
#pragma unroll
                for (int p = 0; p < 4; p++) {
                    const int cur = p & 1;
                    if (p < 3) ldm_x4(b[cur ^ 1], stBl + colx + (uint32_t)((p + 1) * 2048));
                    mma_f16(acc[0][2*p],   a0, b[cur][0], b[cur][2]);
                    mma_f16(acc[0][2*p+1], a0, b[cur][1], b[cur][3]);
                    mma_f16(acc[1][2*p],   a1, b[cur][0], b[cur][2]);
                    mma_f16(acc[1][2*p+1], a1, b[cur][1], b[cur][3]);
                }
            }
        }
    }

    if (LOSSFUSE) __syncthreads();   // smem stages reused for logits below

    float* lg = (float*)smem;        // [128][68] when LOSSFUSE

    // ---- epilogue ----
#pragma unroll
    for (int mi = 0; mi < 2; mi++) {
#pragma unroll
        for (int nj = 0; nj < 8; nj++) {
            int colg = n0 + wn * 64 + nj * 8 + q4 * 2;
#pragma unroll
            for (int half = 0; half < 2; half++) {
                int rowg = m0 + wm * 32 + mi * 16 + r8 + half * 8;
                float v0 = acc[mi][nj][half * 2 + 0];
                float v1 = acc[mi][nj][half * 2 + 1];
                if (HASBIAS) { v0 += bias[colg]; v1 += bias[colg + 1]; }
                if (RELU) { v0 = fmaxf(v0, 0.f); v1 = fmaxf(v1, 0.f); }
                if (HALFOUT) {
                    __half2 hp;
                    hp.x = __float2half_rn(v0);
                    hp.y = __float2half_rn(v1);
                    *(__half2*)(Ch + (size_t)rowg * Npad + colg) = hp;
                } else {
                    if (colg < Nreal)     Cf[(size_t)rowg * ldc + colg]     = v0;
                    if (colg + 1 < Nreal) Cf[(size_t)rowg * ldc + colg + 1] = v1;
                    if (LOSSFUSE) {
                        int r = rowg - m0;
                        if (colg < Vn)     lg[r * 68 + colg]     = v0;
                        if (colg + 1 < Vn) lg[r * 68 + colg + 1] = v1;
                    }
                }
            }
        }
    }

    if (LOSSFUSE) {
        __syncthreads();
        for (int r = wid; r < 128; r += 8) {
            const float* row = lg + r * 68;
            float v0 = row[lane];
            float v1 = row[lane + 32];
            float v2 = (lane == 0) ? row[64] : -1e30f;
            float mx = fmaxf(fmaxf(v0, v1), v2);
#pragma unroll
            for (int o = 16; o; o >>= 1) mx = fmaxf(mx, __shfl_xor_sync(0xffffffffu, mx, o));
            float se = __expf(v0 - mx) + __expf(v1 - mx) + ((lane == 0) ? __expf(v2 - mx) : 0.f);
#pragma unroll
            for (int o = 16; o; o >>= 1) se += __shfl_xor_sync(0xffffffffu, se, o);
            if (lane == 0) {
                int rowg = m0 + r;
                int tg = targets[rowg];
                g_rowloss[rowg] = -(row[tg] - mx - __logf(se));
            }
        }
    }
}

// ---------------- attention: block per (b,h), warp per row ------------------
__global__ __launch_bounds__(256) void attn_kernel() {
    int b = blockIdx.x / Hn;
    int h = blockIdx.x - b * Hn;
    int tid = threadIdx.x;
    int w = tid >> 5, lane = tid & 31;

    __shared__ float4 ks[Tn];
    __shared__ float4 vs[Tn];

    {
        int base = (b * Tn + tid) * 72;
        ks[tid] = *(const float4*)&g_qkv[base + 24 + h * 4];
        vs[tid] = *(const float4*)&g_qkv[base + 48 + h * 4];
    }
    __syncthreads();

    const float scale = 0.05103103630798287f;  // 1/sqrt(384)

    for (int t = w; t < Tn; t += 8) {
        float4 q = *(const float4*)&g_qkv[(b * Tn + t) * 72 + h * 4];
        q.x *= scale; q.y *= scale; q.z *= scale; q.w *= scale;
        float l = 0.f, ax = 0.f, ay = 0.f, az = 0.f, aw = 0.f;
        for (int s = lane; s <= t; s += 32) {
            float4 k = ks[s];
            float p = __expf(q.x*k.x + q.y*k.y + q.z*k.z + q.w*k.w);
            float4 v = vs[s];
            l += p;
            ax = fmaf(p, v.x, ax);
            ay = fmaf(p, v.y, ay);
            az = fmaf(p, v.z, az);
            aw = fmaf(p, v.w, aw);
        }
#pragma unroll
        for (int o = 16; o; o >>= 1) {
            l  += __shfl_xor_sync(0xffffffffu, l,  o);
            ax += __shfl_xor_sync(0xffffffffu, ax, o);
            ay += __shfl_xor_sync(0xffffffffu, ay, o);
            az += __shfl_xor_sync(0xffffffffu, az, o);
            aw += __shfl_xor_sync(0xffffffffu, aw, o);
        }
        if (lane == 0) {
            float inv = 1.f / l;
            size_t rb = (size_t)(b * Tn + t) * 64 + h * 4;
            __half2 p0, p1;
            p0.x = __float2half_rn(ax * inv);
            p0.y = __float2half_rn(ay * inv);
            p1.x = __float2half_rn(az * inv);
            p1.y = __float2half_rn(aw * inv);
            *(__half2*)(g_att + rb)     = p0;
            *(__half2*)(g_att + rb + 2) = p1;
        }
    }

    if (h == 0) {
        size_t rb = (size_t)(b * Tn + tid) * 64;
        __half2 z; z.x = __float2half_rn(0.f); z.y = z.x;
#pragma unroll
        for (int c = 24; c < 64; c += 2)
            *(__half2*)(g_att + rb + c) = z;
    }
}

// ---------------- loss reduce ------------------------------------------------
__global__ __launch_bounds__(256) void loss_reduce_kernel(float* __restrict__ out,
                                                          int out_size) {
    __shared__ float sm[256];
    int tid = threadIdx.x;
    float s = 0.f;
    for (int i = tid; i < BTn; i += 256) s += g_rowloss[i];
    sm[tid] = s;
    __syncthreads();
    for (int st = 128; st > 0; st >>= 1) {
        if (tid < st) sm[tid] += sm[tid + st];
        __syncthreads();
    }
    float loss = sm[0] * (1.f / BTn);
    for (int i = BTn * Vn + tid; i < out_size; i += 256) out[i] = loss;
}

// ---------------------------------------------------------------------------
extern "C" void kernel_launch(void* const* d_in, const int* in_sizes, int n_in,
                              void* d_out, int out_size) {
    const int*   idx     = (const int*)d_in[0];
    const int*   targets = (const int*)d_in[1];
    const float* tok     = (const float*)d_in[2];
    const float* pos     = (const float*)d_in[3];
    const float* Wq      = (const float*)d_in[4];
    const float* Wk      = (const float*)d_in[5];
    const float* Wv      = (const float*)d_in[6];
    const float* Wproj   = (const float*)d_in[7];
    const float* bproj   = (const float*)d_in[8];
    const float* W1      = (const float*)d_in[9];
    const float* b1      = (const float*)d_in[10];
    const float* W2      = (const float*)d_in[11];
    const float* b2      = (const float*)d_in[12];
    const float* Wlm     = (const float*)d_in[13];
    const float* blm     = (const float*)d_in[14];
    float* out = (float*)d_out;

    void *px, *pbqh, *pbql, *pqkv, *pat, *pbph, *pbpl;
    void *px2, *pb1h, *ph, *pb2h, *px3, *pblh, *pbll;
    cudaGetSymbolAddress(&px, g_x);
    cudaGetSymbolAddress(&pbqh, g_bqkvh); cudaGetSymbolAddress(&pbql, g_bqkvl);
    cudaGetSymbolAddress(&pqkv, g_qkv);
    cudaGetSymbolAddress(&pat, g_att);
    cudaGetSymbolAddress(&pbph, g_bprojh); cudaGetSymbolAddress(&pbpl, g_bprojl);
    cudaGetSymbolAddress(&px2, g_x2);
    cudaGetSymbolAddress(&pb1h, g_b1h);
    cudaGetSymbolAddress(&ph, g_h);
    cudaGetSymbolAddress(&pb2h, g_b2h);
    cudaGetSymbolAddress(&px3, g_x3);
    cudaGetSymbolAddress(&pblh, g_blmh);  cudaGetSymbolAddress(&pbll, g_blml);

    const int SMEM2 = NSTAGE * 3 * TILE_B;  // 98304 (two-product)
    const int SMEM1 = NSTAGE * 2 * TILE_B;  // 65536 (single-product)
    cudaFuncSetAttribute(tc_gemm<false,false,false,false,true >, cudaFuncAttributeMaxDynamicSharedMemorySize, SMEM2);
    cudaFuncSetAttribute(tc_gemm<false,true, true, false,true >, cudaFuncAttributeMaxDynamicSharedMemorySize, SMEM2);
    cudaFuncSetAttribute(tc_gemm<true, true, true, false,false>, cudaFuncAttributeMaxDynamicSharedMemorySize, SMEM1);
    cudaFuncSetAttribute(tc_gemm<false,true, true, false,false>, cudaFuncAttributeMaxDynamicSharedMemorySize, SMEM1);
    cudaFuncSetAttribute(tc_gemm<false,true, false,true, true >, cudaFuncAttributeMaxDynamicSharedMemorySize, SMEM2);

    {
        const int total = PACKT + BTn * Cn;
        pack_embed<<<(total + 255)/256, 256>>>(Wq, Wk, Wv, Wproj, W1, W2, Wlm,
                                               idx, tok, pos);                  // L1
    }

    // qkv: [BT,384] @ [384,72pad128] -> float g_qkv (2-product)                // L2
    tc_gemm<false,false,false,false,true><<<dim3(1, BTn/128), 256, SMEM2>>>(
        (const __half*)px, Cn,
        (const __half*)pbqh, (const __half*)pbql,
        nullptr, (float*)pqkv, 72, 72, nullptr, 0, nullptr);

    attn_kernel<<<128 * Hn, 256>>>();                                           // L3

    // proj: [BT,64pad] @ [64,384] + bproj -> fp16 x2 (2-product)               // L4
    tc_gemm<false,true,true,false,true><<<dim3(3, BTn/128), 256, SMEM2>>>(
        (const __half*)pat, 64,
        (const __half*)pbph, (const __half*)pbpl,
        bproj, nullptr, 0, 0, (__half*)px2, Cn, nullptr);

    // ffn1: relu([BT,384] @ [384,1536] + b1) -> fp16 h (single-product)
    tc_gemm<true,true,true,false,false><<<dim3(12, BTn/128), 256, SMEM1>>>(
        (const __half*)px2, Cn,
        (const __half*)pb1h, nullptr,
        b1, nullptr, 0, 0, (__half*)ph, Fn, nullptr);

    // ffn2: [BT,1536] @ [1536,384] + b2 -> fp16 x3 (single-product)
    tc_gemm<false,true,true,false,false><<<dim3(3, BTn/128), 256, SMEM1>>>(
        (const __half*)ph, Fn,
        (const __half*)pb2h, nullptr,
        b2, nullptr, 0, 0, (__half*)px3, Cn, nullptr);

    // lm: [BT,384] @ [384,65pad128] + blm -> logits + fused rowloss (2-product)
    tc_gemm<false,true,false,true,true><<<dim3(1, BTn/128), 256, SMEM2>>>(
        (const __half*)px3, Cn,
        (const __half*)pblh, (const __half*)pbll,
        blm, out, Vn, Vn, nullptr, 0, targets);

    loss_reduce_kernel<<<1, 256>>>(out, out_size);
}

// round 15
// speedup vs baseline: 1.5170x; 1.0416x over previous
#include <cuda_runtime.h>
#include <cuda_fp16.h>
#include <cstdint>

#define BTn 32768
#define Tn  256
#define Cn  384
#define Hn  6
#define Vn  65
#define Fn  1536

// ---------------- scratch (device globals; allocation-free rule) -----------
__device__ __half g_x[BTn*Cn];                      // embeddings fp16
__device__ __half g_bqkvh[128*Cn];                  // qkv W fp16 [Npad=128,K=384]
__device__ float  g_qkv[BTn*72];                    // qkv activations (f32)
__device__ __half g_att[BTn*64];                    // attn out fp16, Kpad=64
__device__ __half g_bprojh[Cn*64];                  // proj W fp16 [384,Kpad=64]
__device__ __half g_x2[BTn*Cn];                     // proj out fp16
__device__ __half g_b1h[Fn*Cn];                     // W1^T fp16 [1536,384]
__device__ __half g_h[BTn*Fn];                      // ffn hidden fp16
__device__ __half g_b2h[Cn*Fn];                     // W2^T fp16 [384,1536]
__device__ __half g_x3[BTn*Cn];                     // ffn out fp16
__device__ __half g_blmh[128*Cn];                   // Wlm^T fp16 [Npad=128,384]
__device__ float  g_rowloss[BTn];

// ---------------- helpers ----------------------------------------------
__device__ __forceinline__ uint32_t smem_u32(const void* p) {
    return (uint32_t)__cvta_generic_to_shared(p);
}

__device__ __forceinline__ void cp16(uint32_t dst, const void* src) {
    asm volatile("cp.async.cg.shared.global [%0], [%1], 16;" :: "r"(dst), "l"(src));
}
#define CP_COMMIT() asm volatile("cp.async.commit_group;" ::: "memory")
#define CP_WAIT(n)  asm volatile("cp.async.wait_group %0;" :: "n"(n) : "memory")

__device__ __forceinline__ void mma_f16(float* d, const uint32_t* a, uint32_t b0, uint32_t b1) {
    asm volatile(
        "mma.sync.aligned.m16n8k16.row.col.f32.f16.f16.f32 "
        "{%0,%1,%2,%3}, {%4,%5,%6,%7}, {%8,%9}, {%0,%1,%2,%3};"
        : "+f"(d[0]), "+f"(d[1]), "+f"(d[2]), "+f"(d[3])
        : "r"(a[0]), "r"(a[1]), "r"(a[2]), "r"(a[3]), "r"(b0), "r"(b1));
}

__device__ __forceinline__ void ldm_x4(uint32_t* r, uint32_t addr) {
    asm volatile("ldmatrix.sync.aligned.m8n8.x4.shared.b16 {%0,%1,%2,%3}, [%4];"
        : "=r"(r[0]), "=r"(r[1]), "=r"(r[2]), "=r"(r[3]) : "r"(addr));
}

// ---------------- fused pack + embed (one launch) ---------------------------
#define S0 (128*Cn)
#define S1 (Cn*64)
#define S2 (Fn*Cn)
#define S3 (Cn*Fn)
#define S4 (128*Cn)
#define PACKT (S0 + S1 + S2 + S3 + S4)

__global__ void pack_embed(const float* __restrict__ Wq, const float* __restrict__ Wk,
                           const float* __restrict__ Wv, const float* __restrict__ Wproj,
                           const float* __restrict__ W1, const float* __restrict__ W2,
                           const float* __restrict__ Wlm,
                           const int* __restrict__ idx, const float* __restrict__ tok,
                           const float* __restrict__ pos) {
    int i = blockIdx.x * blockDim.x + threadIdx.x;
    if (i < PACKT) {
        if (i < S0) {
            int o = i, n = o / Cn, k = o - n * Cn;
            float v = 0.f;
            if (n < 72) {
                int g = n / 24, rem = n - g * 24, h = rem >> 2, d = rem & 3;
                const float* W = (g == 0) ? Wq : (g == 1) ? Wk : Wv;
                v = W[(h * Cn + k) * 4 + d];
            }
            g_bqkvh[o] = __float2half_rn(v);
        } else if (i < S0 + S1) {
            int o = i - S0, n = o >> 6, k = o & 63;
            g_bprojh[o] = __float2half_rn((k < 24) ? Wproj[k * Cn + n] : 0.f);
        } else if (i < S0 + S1 + S2) {
            int o = i - S0 - S1, n = o / Cn, k = o - n * Cn;
            g_b1h[o] = __float2half_rn(W1[(size_t)k * Fn + n]);
        } else if (i < S0 + S1 + S2 + S3) {
            int o = i - S0 - S1 - S2, n = o / Fn, k = o - n * Fn;
            g_b2h[o] = __float2half_rn(W2[(size_t)k * Cn + n]);
        } else {
            int o = i - S0 - S1 - S2 - S3, n = o / Cn, k = o - n * Cn;
            g_blmh[o] = __float2half_rn((n < Vn) ? Wlm[k * Vn + n] : 0.f);
        }
        return;
    }
    int e = i - PACKT;
    if (e >= BTn * Cn) return;
    int bt = e / Cn, c = e - bt * Cn;
    int t = bt & (Tn - 1);
    g_x[e] = __float2half_rn(tok[__ldg(&idx[bt]) * Cn + c] + pos[t * Cn + c]);
}

// ---------------- fp16 single-product GEMM, BK=64, 2-stage ------------------
// C[M,N] = A[M,K] @ B^T. 128x128 CTA tile, BK=64, 8 warps (4M x 2N),
// warp tile 32x64. One CP_WAIT + one barrier per 64-K chunk.
// smem tile: [128 rows][64 fp16] = 128B rows, XOR-8 swizzle on 16B chunks.
// LOSSFUSE: after epilogue, compute per-row NLL from logits (lm kernel only).
#define TILE_B 16384
#define STAGE_B (2 * TILE_B)     // A, B = 32768
#define NSTAGE 2

template <bool RELU, bool HASBIAS, bool HALFOUT, bool LOSSFUSE>
__global__ __launch_bounds__(256, 2) void tc_gemm(
    const __half* __restrict__ A, int Kpad,
    const __half* __restrict__ Bh,
    const float* __restrict__ bias,
    float* __restrict__ Cf, int ldc, int Nreal,
    __half* __restrict__ Ch, int Npad,
    const int* __restrict__ targets)
{
    extern __shared__ char smem[];
    const int tid  = threadIdx.x;
    const int lane = tid & 31, wid = tid >> 5;
    const int wm = wid & 3, wn = wid >> 2;       // 4x2 warp grid, 32x64 tiles
    const int m0 = blockIdx.y * 128, n0 = blockIdx.x * 128;

    const __half* gsrc[2] = {
        A  + (size_t)m0 * Kpad,
        Bh + (size_t)n0 * Kpad };

    const int nk = Kpad / 64;
    const uint32_t sbase = smem_u32(smem);

    auto load_stage = [&](int stage, int c) {
        uint32_t dst0 = sbase + stage * STAGE_B;
        int kc0 = c * 64;
#pragma unroll
        for (int tile = 0; tile < 2; tile++) {
            const __half* g = gsrc[tile] + kc0;
#pragma unroll
            for (int t = 0; t < 4; t++) {
                int j = tid + t * 256;               // 0..1023
                int row = j >> 3, sx = j & 7;
                uint32_t sw = (uint32_t)(row * 128 + ((sx ^ (row & 7)) << 4));
                cp16(dst0 + tile * TILE_B + sw, g + (size_t)row * Kpad + sx * 8);
            }
        }
        CP_COMMIT();
    };

    float acc[2][8][4];
#pragma unroll
    for (int mi = 0; mi < 2; mi++)
#pragma unroll
        for (int nj = 0; nj < 8; nj++)
#pragma unroll
            for (int q = 0; q < 4; q++) acc[mi][nj][q] = 0.f;

    load_stage(0, 0);

    // ldmatrix lane addressing (128B rows, XOR-8 swizzle)
    const uint32_t lrow = (uint32_t)(lane & 15);
    const uint32_t lrow128 = lrow * 128;
    const uint32_t xh = (uint32_t)(lane >> 4);
    const uint32_t sxor = lrow & 7;
    const int r8 = lane >> 2, q4 = lane & 3;

    for (int c = 0; c < nk; c++) {
        CP_WAIT(0);
        __syncthreads();
        if (c + 1 < nk) load_stage((c + 1) & 1, c + 1);

        const uint32_t st = sbase + (uint32_t)((c & 1) * STAGE_B);
        const uint32_t stA  = st + (uint32_t)(wm * 4096) + lrow128;
        const uint32_t stBh = st + TILE_B + (uint32_t)(wn * 8192) + lrow128;

#pragma unroll
        for (int ks = 0; ks < 4; ks++) {
            const uint32_t colx = ((2u * (uint32_t)ks + xh) ^ sxor) << 4;
            uint32_t a0[4], a1[4];
            ldm_x4(a0, stA + colx);
            ldm_x4(a1, stA + colx + 2048);
            uint32_t b[2][4];

            ldm_x4(b[0], stBh + colx);
#pragma unroll
            for (int p = 0; p < 4; p++) {
                const int cur = p & 1;
                if (p < 3) ldm_x4(b[cur ^ 1], stBh + colx + (uint32_t)((p + 1) * 2048));
                mma_f16(acc[0][2*p],   a0, b[cur][0], b[cur][2]);
                mma_f16(acc[0][2*p+1], a0, b[cur][1], b[cur][3]);
                mma_f16(acc[1][2*p],   a1, b[cur][0], b[cur][2]);
                mma_f16(acc[1][2*p+1], a1, b[cur][1], b[cur][3]);
            }
        }
    }

    if (LOSSFUSE) __syncthreads();   // smem stages reused for logits below

    float* lg = (float*)smem;        // [128][68] when LOSSFUSE

    // ---- epilogue ----
#pragma unroll
    for (int mi = 0; mi < 2; mi++) {
#pragma unroll
        for (int nj = 0; nj < 8; nj++) {
            int colg = n0 + wn * 64 + nj * 8 + q4 * 2;
#pragma unroll
            for (int half = 0; half < 2; half++) {
                int rowg = m0 + wm * 32 + mi * 16 + r8 + half * 8;
                float v0 = acc[mi][nj][half * 2 + 0];
                float v1 = acc[mi][nj][half * 2 + 1];
                if (HASBIAS) { v0 += bias[colg]; v1 += bias[colg + 1]; }
                if (RELU) { v0 = fmaxf(v0, 0.f); v1 = fmaxf(v1, 0.f); }
                if (HALFOUT) {
                    __half2 hp;
                    hp.x = __float2half_rn(v0);
                    hp.y = __float2half_rn(v1);
                    *(__half2*)(Ch + (size_t)rowg * Npad + colg) = hp;
                } else {
                    if (colg < Nreal)     Cf[(size_t)rowg * ldc + colg]     = v0;
                    if (colg + 1 < Nreal) Cf[(size_t)rowg * ldc + colg + 1] = v1;
                    if (LOSSFUSE) {
                        int r = rowg - m0;
                        if (colg < Vn)     lg[r * 68 + colg]     = v0;
                        if (colg + 1 < Vn) lg[r * 68 + colg + 1] = v1;
                    }
                }
            }
        }
    }

    if (LOSSFUSE) {
        __syncthreads();
        for (int r = wid; r < 128; r += 8) {
            const float* row = lg + r * 68;
            float v0 = row[lane];
            float v1 = row[lane + 32];
            float v2 = (lane == 0) ? row[64] : -1e30f;
            float mx = fmaxf(fmaxf(v0, v1), v2);
#pragma unroll
            for (int o = 16; o; o >>= 1) mx = fmaxf(mx, __shfl_xor_sync(0xffffffffu, mx, o));
            float se = __expf(v0 - mx) + __expf(v1 - mx) + ((lane == 0) ? __expf(v2 - mx) : 0.f);
#pragma unroll
            for (int o = 16; o; o >>= 1) se += __shfl_xor_sync(0xffffffffu, se, o);
            if (lane == 0) {
                int rowg = m0 + r;
                int tg = targets[rowg];
                g_rowloss[rowg] = -(row[tg] - mx - __logf(se));
            }
        }
    }
}

// ---------------- attention: block per (b,h), warp per row ------------------
__global__ __launch_bounds__(256) void attn_kernel() {
    int b = blockIdx.x / Hn;
    int h = blockIdx.x - b * Hn;
    int tid = threadIdx.x;
    int w = tid >> 5, lane = tid & 31;

    __shared__ float4 ks[Tn];
    __shared__ float4 vs[Tn];

    {
        int base = (b * Tn + tid) * 72;
        ks[tid] = *(const float4*)&g_qkv[base + 24 + h * 4];
        vs[tid] = *(const float4*)&g_qkv[base + 48 + h * 4];
    }
    __syncthreads();

    const float scale = 0.05103103630798287f;  // 1/sqrt(384)

    for (int t = w; t < Tn; t += 8) {
        float4 q = *(const float4*)&g_qkv[(b * Tn + t) * 72 + h * 4];
        q.x *= scale; q.y *= scale; q.z *= scale; q.w *= scale;
        float l = 0.f, ax = 0.f, ay = 0.f, az = 0.f, aw = 0.f;
        for (int s = lane; s <= t; s += 32) {
            float4 k = ks[s];
            float p = __expf(q.x*k.x + q.y*k.y + q.z*k.z + q.w*k.w);
            float4 v = vs[s];
            l += p;
            ax = fmaf(p, v.x, ax);
            ay = fmaf(p, v.y, ay);
            az = fmaf(p, v.z, az);
            aw = fmaf(p, v.w, aw);
        }
#pragma unroll
        for (int o = 16; o; o >>= 1) {
            l  += __shfl_xor_sync(0xffffffffu, l,  o);
            ax += __shfl_xor_sync(0xffffffffu, ax, o);
            ay += __shfl_xor_sync(0xffffffffu, ay, o);
            az += __shfl_xor_sync(0xffffffffu, az, o);
            aw += __shfl_xor_sync(0xffffffffu, aw, o);
        }
        if (lane == 0) {
            float inv = 1.f / l;
            size_t rb = (size_t)(b * Tn + t) * 64 + h * 4;
            __half2 p0, p1;
            p0.x = __float2half_rn(ax * inv);
            p0.y = __float2half_rn(ay * inv);
            p1.x = __float2half_rn(az * inv);
            p1.y = __float2half_rn(aw * inv);
            *(__half2*)(g_att + rb)     = p0;
            *(__half2*)(g_att + rb + 2) = p1;
        }
    }

    if (h == 0) {
        size_t rb = (size_t)(b * Tn + tid) * 64;
        __half2 z; z.x = __float2half_rn(0.f); z.y = z.x;
#pragma unroll
        for (int c = 24; c < 64; c += 2)
            *(__half2*)(g_att + rb + c) = z;
    }
}

// ---------------- loss reduce ------------------------------------------------
__global__ __launch_bounds__(256) void loss_reduce_kernel(float* __restrict__ out,
                                                          int out_size) {
    __shared__ float sm[256];
    int tid = threadIdx.x;
    float s = 0.f;
    for (int i = tid; i < BTn; i += 256) s += g_rowloss[i];
    sm[tid] = s;
    __syncthreads();
    for (int st = 128; st > 0; st >>= 1) {
        if (tid < st) sm[tid] += sm[tid + st];
        __syncthreads();
    }
    float loss = sm[0] * (1.f / BTn);
    for (int i = BTn * Vn + tid; i < out_size; i += 256) out[i] = loss;
}

// ---------------------------------------------------------------------------
extern "C" void kernel_launch(void* const* d_in, const int* in_sizes, int n_in,
                              void* d_out, int out_size) {
    const int*   idx     = (const int*)d_in[0];
    const int*   targets = (const int*)d_in[1];
    const float* tok     = (const float*)d_in[2];
    const float* pos     = (const float*)d_in[3];
    const float* Wq      = (const float*)d_in[4];
    const float* Wk      = (const float*)d_in[5];
    const float* Wv      = (const float*)d_in[6];
    const float* Wproj   = (const float*)d_in[7];
    const float* bproj   = (const float*)d_in[8];
    const float* W1      = (const float*)d_in[9];
    const float* b1      = (const float*)d_in[10];
    const float* W2      = (const float*)d_in[11];
    const float* b2      = (const float*)d_in[12];
    const float* Wlm     = (const float*)d_in[13];
    const float* blm     = (const float*)d_in[14];
    float* out = (float*)d_out;

    void *px, *pbqh, *pqkv, *pat, *pbph;
    void *px2, *pb1h, *ph, *pb2h, *px3, *pblh;
    cudaGetSymbolAddress(&px, g_x);
    cudaGetSymbolAddress(&pbqh, g_bqkvh);
    cudaGetSymbolAddress(&pqkv, g_qkv);
    cudaGetSymbolAddress(&pat, g_att);
    cudaGetSymbolAddress(&pbph, g_bprojh);
    cudaGetSymbolAddress(&px2, g_x2);
    cudaGetSymbolAddress(&pb1h, g_b1h);
    cudaGetSymbolAddress(&ph, g_h);
    cudaGetSymbolAddress(&pb2h, g_b2h);
    cudaGetSymbolAddress(&px3, g_x3);
    cudaGetSymbolAddress(&pblh, g_blmh);

    const int SMEM = NSTAGE * STAGE_B;  // 65536
    cudaFuncSetAttribute(tc_gemm<false,false,false,false>, cudaFuncAttributeMaxDynamicSharedMemorySize, SMEM);
    cudaFuncSetAttribute(tc_gemm<false,true, true, false>, cudaFuncAttributeMaxDynamicSharedMemorySize, SMEM);
    cudaFuncSetAttribute(tc_gemm<true, true, true, false>, cudaFuncAttributeMaxDynamicSharedMemorySize, SMEM);
    cudaFuncSetAttribute(tc_gemm<false,true, false,true >, cudaFuncAttributeMaxDynamicSharedMemorySize, SMEM);

    {
        const int total = PACKT + BTn * Cn;
        pack_embed<<<(total + 255)/256, 256>>>(Wq, Wk, Wv, Wproj, W1, W2, Wlm,
                                               idx, tok, pos);                  // L1
    }

    // qkv: [BT,384] @ [384,72pad128] -> float g_qkv                            // L2
    tc_gemm<false,false,false,false><<<dim3(1, BTn/128), 256, SMEM>>>(
        (const __half*)px, Cn, (const __half*)pbqh,
        nullptr, (float*)pqkv, 72, 72, nullptr, 0, nullptr);

    attn_kernel<<<128 * Hn, 256>>>();                                           // L3

    // proj: [BT,64pad] @ [64,384] + bproj -> fp16 x2                           // L4
    tc_gemm<false,true,true,false><<<dim3(3, BTn/128), 256, SMEM>>>(
        (const __half*)pat, 64, (const __half*)pbph,
        bproj, nullptr, 0, 0, (__half*)px2, Cn, nullptr);

    // ffn1: relu([BT,384] @ [384,1536] + b1) -> fp16 h
    tc_gemm<true,true,true,false><<<dim3(12, BTn/128), 256, SMEM>>>(
        (const __half*)px2, Cn, (const __half*)pb1h,
        b1, nullptr, 0, 0, (__half*)ph, Fn, nullptr);

    // ffn2: [BT,1536] @ [1536,384] + b2 -> fp16 x3
    tc_gemm<false,true,true,false><<<dim3(3, BTn/128), 256, SMEM>>>(
        (const __half*)ph, Fn, (const __half*)pb2h,
        b2, nullptr, 0, 0, (__half*)px3, Cn, nullptr);

    // lm: [BT,384] @ [384,65pad128] + blm -> logits + fused rowloss
    tc_gemm<false,true,false,true><<<dim3(1, BTn/128), 256, SMEM>>>(
        (const __half*)px3, Cn, (const __half*)pblh,
        blm, out, Vn, Vn, nullptr, 0, targets);

    loss_reduce_kernel<<<1, 256>>>(out, out_size);
}

// round 16
// speedup vs baseline: 1.5996x; 1.0544x over previous
#include <cuda_runtime.h>
#include <cuda_fp16.h>
#include <cstdint>

#define BTn 32768
#define Tn  256
#define Cn  384
#define Hn  6
#define Vn  65
#define Fn  1536

// ---------------- scratch (device globals; allocation-free rule) -----------
__device__ __half g_bqkvh[128*Cn];                  // qkv W fp16 [Npad=128,K=384]
__device__ float  g_qkv[BTn*72];                    // qkv activations (f32)
__device__ __half g_att[BTn*64];                    // attn out fp16, Kpad=64
__device__ __half g_bprojh[Cn*64];                  // proj W fp16 [384,Kpad=64]
__device__ __half g_x2[BTn*Cn];                     // proj out fp16
__device__ __half g_b1h[Fn*Cn];                     // W1^T fp16 [1536,384]
__device__ __half g_h[BTn*Fn];                      // ffn hidden fp16
__device__ __half g_b2h[Cn*Fn];                     // W2^T fp16 [384,1536]
__device__ __half g_x3[BTn*Cn];                     // ffn out fp16
__device__ __half g_blmh[128*Cn];                   // Wlm^T fp16 [Npad=128,384]
__device__ float  g_rowloss[BTn];

// ---------------- helpers ----------------------------------------------
__device__ __forceinline__ uint32_t smem_u32(const void* p) {
    return (uint32_t)__cvta_generic_to_shared(p);
}

__device__ __forceinline__ void cp16(uint32_t dst, const void* src) {
    asm volatile("cp.async.cg.shared.global [%0], [%1], 16;" :: "r"(dst), "l"(src));
}
#define CP_COMMIT() asm volatile("cp.async.commit_group;" ::: "memory")
#define CP_WAIT(n)  asm volatile("cp.async.wait_group %0;" :: "n"(n) : "memory")

__device__ __forceinline__ void mma_f16(float* d, const uint32_t* a, uint32_t b0, uint32_t b1) {
    asm volatile(
        "mma.sync.aligned.m16n8k16.row.col.f32.f16.f16.f32 "
        "{%0,%1,%2,%3}, {%4,%5,%6,%7}, {%8,%9}, {%0,%1,%2,%3};"
        : "+f"(d[0]), "+f"(d[1]), "+f"(d[2]), "+f"(d[3])
        : "r"(a[0]), "r"(a[1]), "r"(a[2]), "r"(a[3]), "r"(b0), "r"(b1));
}

__device__ __forceinline__ void ldm_x4(uint32_t* r, uint32_t addr) {
    asm volatile("ldmatrix.sync.aligned.m8n8.x4.shared.b16 {%0,%1,%2,%3}, [%4];"
        : "=r"(r[0]), "=r"(r[1]), "=r"(r[2]), "=r"(r[3]) : "r"(addr));
}

// ---------------- weight pack (one small launch) ----------------------------
#define S0 (128*Cn)
#define S1 (Cn*64)
#define S2 (Fn*Cn)
#define S3 (Cn*Fn)
#define S4 (128*Cn)
#define PACKT (S0 + S1 + S2 + S3 + S4)

__global__ void pack_weights(const float* __restrict__ Wq, const float* __restrict__ Wk,
                             const float* __restrict__ Wv, const float* __restrict__ Wproj,
                             const float* __restrict__ W1, const float* __restrict__ W2,
                             const float* __restrict__ Wlm) {
    int i = blockIdx.x * blockDim.x + threadIdx.x;
    if (i >= PACKT) return;
    if (i < S0) {
        int o = i, n = o / Cn, k = o - n * Cn;
        float v = 0.f;
        if (n < 72) {
            int g = n / 24, rem = n - g * 24, h = rem >> 2, d = rem & 3;
            const float* W = (g == 0) ? Wq : (g == 1) ? Wk : Wv;
            v = W[(h * Cn + k) * 4 + d];
        }
        g_bqkvh[o] = __float2half_rn(v);
    } else if (i < S0 + S1) {
        int o = i - S0, n = o >> 6, k = o & 63;
        g_bprojh[o] = __float2half_rn((k < 24) ? Wproj[k * Cn + n] : 0.f);
    } else if (i < S0 + S1 + S2) {
        int o = i - S0 - S1, n = o / Cn, k = o - n * Cn;
        g_b1h[o] = __float2half_rn(W1[(size_t)k * Fn + n]);
    } else if (i < S0 + S1 + S2 + S3) {
        int o = i - S0 - S1 - S2, n = o / Fn, k = o - n * Fn;
        g_b2h[o] = __float2half_rn(W2[(size_t)k * Cn + n]);
    } else {
        int o = i - S0 - S1 - S2 - S3, n = o / Cn, k = o - n * Cn;
        g_blmh[o] = __float2half_rn((n < Vn) ? Wlm[k * Vn + n] : 0.f);
    }
}

// ---------------- fp16 single-product GEMM, BK=64, 3-stage ------------------
// C[M,N] = A[M,K] @ B^T. 128x128 CTA tile, BK=64, 8 warps (4M x 2N),
// warp tile 32x64. Graded CP_WAIT tail; prefetch distance 2 chunks.
// smem tile: [128 rows][64 fp16] = 128B rows, XOR-8 swizzle on 16B chunks.
// EMBED: A tile is built in-kernel (tok[idx[row]] + pos[row%T] -> fp16 STS);
//        cp.async group then carries only the B tile (wait logic unchanged).
// LOSSFUSE: after epilogue, compute per-row NLL from logits (lm kernel only).
#define TILE_B 16384
#define STAGE_B (2 * TILE_B)     // A, B = 32768
#define NSTAGE 3

template <bool RELU, bool HASBIAS, bool HALFOUT, bool LOSSFUSE, bool EMBED>
__global__ __launch_bounds__(256, 2) void tc_gemm(
    const __half* __restrict__ A, int Kpad,
    const __half* __restrict__ Bh,
    const float* __restrict__ bias,
    float* __restrict__ Cf, int ldc, int Nreal,
    __half* __restrict__ Ch, int Npad,
    const int* __restrict__ targets,
    const int* __restrict__ idx, const float* __restrict__ tok,
    const float* __restrict__ pos)
{
    extern __shared__ char smem[];
    const int tid  = threadIdx.x;
    const int lane = tid & 31, wid = tid >> 5;
    const int wm = wid & 3, wn = wid >> 2;       // 4x2 warp grid, 32x64 tiles
    const int m0 = blockIdx.y * 128, n0 = blockIdx.x * 128;

    const __half* gA = A  + (EMBED ? 0 : (size_t)m0 * Kpad);
    const __half* gB = Bh + (size_t)n0 * Kpad;

    const int nk = Kpad / 64;
    const uint32_t sbase = smem_u32(smem);

    auto load_stage = [&](int stage, int c) {
        uint32_t dst0 = sbase + (uint32_t)(stage * STAGE_B);
        int kc0 = c * 64;
        if (EMBED) {
            // A tile via vocab gather (tok table is L1/L2 resident: 65x384 f32)
#pragma unroll
            for (int t = 0; t < 4; t++) {
                int j = tid + t * 256;               // 0..1023
                int row = j >> 3, sx = j & 7;
                int bt = m0 + row;
                int k = kc0 + sx * 8;
                const float* tp = tok + (size_t)__ldg(&idx[bt]) * Cn + k;
                const float* pp = pos + (size_t)(bt & (Tn - 1)) * Cn + k;
                float4 u0 = *(const float4*)tp;
                float4 u1 = *(const float4*)(tp + 4);
                float4 v0 = *(const float4*)pp;
                float4 v1 = *(const float4*)(pp + 4);
                __half2 h[4];
                h[0] = __floats2half2_rn(u0.x + v0.x, u0.y + v0.y);
                h[1] = __floats2half2_rn(u0.z + v0.z, u0.w + v0.w);
                h[2] = __floats2half2_rn(u1.x + v1.x, u1.y + v1.y);
                h[3] = __floats2half2_rn(u1.z + v1.z, u1.w + v1.w);
                uint32_t sw = (uint32_t)(row * 128 + ((sx ^ (row & 7)) << 4));
                *(uint4*)(smem + stage * STAGE_B + sw) = *(uint4*)h;
            }
        } else {
#pragma unroll
            for (int t = 0; t < 4; t++) {
                int j = tid + t * 256;
                int row = j >> 3, sx = j & 7;
                uint32_t sw = (uint32_t)(row * 128 + ((sx ^ (row & 7)) << 4));
                cp16(dst0 + sw, gA + (size_t)row * Kpad + kc0 + sx * 8);
            }
        }
#pragma unroll
        for (int t = 0; t < 4; t++) {
            int j = tid + t * 256;
            int row = j >> 3, sx = j & 7;
            uint32_t sw = (uint32_t)(row * 128 + ((sx ^ (row & 7)) << 4));
            cp16(dst0 + TILE_B + sw, gB + (size_t)row * Kpad + kc0 + sx * 8);
        }
        CP_COMMIT();
    };

    float acc[2][8][4];
#pragma unroll
    for (int mi = 0; mi < 2; mi++)
#pragma unroll
        for (int nj = 0; nj < 8; nj++)
#pragma unroll
            for (int q = 0; q < 4; q++) acc[mi][nj][q] = 0.f;

    load_stage(0, 0);
    if (nk > 1) load_stage(1, 1);

    // ldmatrix lane addressing (128B rows, XOR-8 swizzle)
    const uint32_t lrow = (uint32_t)(lane & 15);
    const uint32_t lrow128 = lrow * 128;
    const uint32_t xh = (uint32_t)(lane >> 4);
    const uint32_t sxor = lrow & 7;
    const int r8 = lane >> 2, q4 = lane & 3;

    for (int c = 0; c < nk; c++) {
        if (c < nk - 1) CP_WAIT(1); else CP_WAIT(0);
        __syncthreads();
        if (c + 2 < nk) load_stage((c + 2) % NSTAGE, c + 2);

        const uint32_t st = sbase + (uint32_t)((c % NSTAGE) * STAGE_B);
        const uint32_t stA  = st + (uint32_t)(wm * 4096) + lrow128;
        const uint32_t stBh = st + TILE_B + (uint32_t)(wn * 8192) + lrow128;

#pragma unroll
        for (int ks = 0; ks < 4; ks++) {
            const uint32_t colx = ((2u * (uint32_t)ks + xh) ^ sxor) << 4;
            uint32_t a0[4], a1[4];
            ldm_x4(a0, stA + colx);
            ldm_x4(a1, stA + colx + 2048);
            uint32_t b[2][4];

            ldm_x4(b[0], stBh + colx);
#pragma unroll
            for (int p = 0; p < 4; p++) {
                const int cur = p & 1;
                if (p < 3) ldm_x4(b[cur ^ 1], stBh + colx + (uint32_t)((p + 1) * 2048));
                mma_f16(acc[0][2*p],   a0, b[cur][0], b[cur][2]);
                mma_f16(acc[0][2*p+1], a0, b[cur][1], b[cur][3]);
                mma_f16(acc[1][2*p],   a1, b[cur][0], b[cur][2]);
                mma_f16(acc[1][2*p+1], a1, b[cur][1], b[cur][3]);
            }
        }
    }

    if (LOSSFUSE) __syncthreads();   // smem stages reused for logits below

    float* lg = (float*)smem;        // [128][68] when LOSSFUSE

    // ---- epilogue ----
#pragma unroll
    for (int mi = 0; mi < 2; mi++) {
#pragma unroll
        for (int nj = 0; nj < 8; nj++) {
            int colg = n0 + wn * 64 + nj * 8 + q4 * 2;
#pragma unroll
            for (int half = 0; half < 2; half++) {
                int rowg = m0 + wm * 32 + mi * 16 + r8 + half * 8;
                float v0 = acc[mi][nj][half * 2 + 0];
                float v1 = acc[mi][nj][half * 2 + 1];
                if (HASBIAS) { v0 += bias[colg]; v1 += bias[colg + 1]; }
                if (RELU) { v0 = fmaxf(v0, 0.f); v1 = fmaxf(v1, 0.f); }
                if (HALFOUT) {
                    __half2 hp;
                    hp.x = __float2half_rn(v0);
                    hp.y = __float2half_rn(v1);
                    *(__half2*)(Ch + (size_t)rowg * Npad + colg) = hp;
                } else {
                    if (colg < Nreal)     Cf[(size_t)rowg * ldc + colg]     = v0;
                    if (colg + 1 < Nreal) Cf[(size_t)rowg * ldc + colg + 1] = v1;
                    if (LOSSFUSE) {
                        int r = rowg - m0;
                        if (colg < Vn)     lg[r * 68 + colg]     = v0;
                        if (colg + 1 < Vn) lg[r * 68 + colg + 1] = v1;
                    }
                }
            }
        }
    }

    if (LOSSFUSE) {
        __syncthreads();
        for (int r = wid; r < 128; r += 8) {
            const float* row = lg + r * 68;
            float v0 = row[lane];
            float v1 = row[lane + 32];
            float v2 = (lane == 0) ? row[64] : -1e30f;
            float mx = fmaxf(fmaxf(v0, v1), v2);
#pragma unroll
            for (int o = 16; o; o >>= 1) mx = fmaxf(mx, __shfl_xor_sync(0xffffffffu, mx, o));
            float se = __expf(v0 - mx) + __expf(v1 - mx) + ((lane == 0) ? __expf(v2 - mx) : 0.f);
#pragma unroll
            for (int o = 16; o; o >>= 1) se += __shfl_xor_sync(0xffffffffu, se, o);
            if (lane == 0) {
                int rowg = m0 + r;
                int tg = targets[rowg];
                g_rowloss[rowg] = -(row[tg] - mx - __logf(se));
            }
        }
    }
}

// ---------------- attention: block per (b,h), warp per row ------------------
__global__ __launch_bounds__(256) void attn_kernel() {
    int b = blockIdx.x / Hn;
    int h = blockIdx.x - b * Hn;
    int tid = threadIdx.x;
    int w = tid >> 5, lane = tid & 31;

    __shared__ float4 ks[Tn];
    __shared__ float4 vs[Tn];

    {
        int base = (b * Tn + tid) * 72;
        ks[tid] = *(const float4*)&g_qkv[base + 24 + h * 4];
        vs[tid] = *(const float4*)&g_qkv[base + 48 + h * 4];
    }
    __syncthreads();

    const float scale = 0.05103103630798287f;  // 1/sqrt(384)

    for (int t = w; t < Tn; t += 8) {
        float4 q = *(const float4*)&g_qkv[(b * Tn + t) * 72 + h * 4];
        q.x *= scale; q.y *= scale; q.z *= scale; q.w *= scale;
        float l = 0.f, ax = 0.f, ay = 0.f, az = 0.f, aw = 0.f;
        for (int s = lane; s <= t; s += 32) {
            float4 k = ks[s];
            float p = __expf(q.x*k.x + q.y*k.y + q.z*k.z + q.w*k.w);
            float4 v = vs[s];
            l += p;
            ax = fmaf(p, v.x, ax);
            ay = fmaf(p, v.y, ay);
            az = fmaf(p, v.z, az);
            aw = fmaf(p, v.w, aw);
        }
#pragma unroll
        for (int o = 16; o; o >>= 1) {
            l  += __shfl_xor_sync(0xffffffffu, l,  o);
            ax += __shfl_xor_sync(0xffffffffu, ax, o);
            ay += __shfl_xor_sync(0xffffffffu, ay, o);
            az += __shfl_xor_sync(0xffffffffu, az, o);
            aw += __shfl_xor_sync(0xffffffffu, aw, o);
        }
        if (lane == 0) {
            float inv = 1.f / l;
            size_t rb = (size_t)(b * Tn + t) * 64 + h * 4;
            __half2 p0, p1;
            p0.x = __float2half_rn(ax * inv);
            p0.y = __float2half_rn(ay * inv);
            p1.x = __float2half_rn(az * inv);
            p1.y = __float2half_rn(aw * inv);
            *(__half2*)(g_att + rb)     = p0;
            *(__half2*)(g_att + rb + 2) = p1;
        }
    }

    if (h == 0) {
        size_t rb = (size_t)(b * Tn + tid) * 64;
        __half2 z; z.x = __float2half_rn(0.f); z.y = z.x;
#pragma unroll
        for (int c = 24; c < 64; c += 2)
            *(__half2*)(g_att + rb + c) = z;
    }
}

// ---------------- loss reduce ------------------------------------------------
__global__ __launch_bounds__(256) void loss_reduce_kernel(float* __restrict__ out,
                                                          int out_size) {
    __shared__ float sm[256];
    int tid = threadIdx.x;
    float s = 0.f;
    for (int i = tid; i < BTn; i += 256) s += g_rowloss[i];
    sm[tid] = s;
    __syncthreads();
    for (int st = 128; st > 0; st >>= 1) {
        if (tid < st) sm[tid] += sm[tid + st];
        __syncthreads();
    }
    float loss = sm[0] * (1.f / BTn);
    for (int i = BTn * Vn + tid; i < out_size; i += 256) out[i] = loss;
}

// ---------------------------------------------------------------------------
extern "C" void kernel_launch(void* const* d_in, const int* in_sizes, int n_in,
                              void* d_out, int out_size) {
    const int*   idx     = (const int*)d_in[0];
    const int*   targets = (const int*)d_in[1];
    const float* tok     = (const float*)d_in[2];
    const float* pos     = (const float*)d_in[3];
    const float* Wq      = (const float*)d_in[4];
    const float* Wk      = (const float*)d_in[5];
    const float* Wv      = (const float*)d_in[6];
    const float* Wproj   = (const float*)d_in[7];
    const float* bproj   = (const float*)d_in[8];
    const float* W1      = (const float*)d_in[9];
    const float* b1      = (const float*)d_in[10];
    const float* W2      = (const float*)d_in[11];
    const float* b2      = (const float*)d_in[12];
    const float* Wlm     = (const float*)d_in[13];
    const float* blm     = (const float*)d_in[14];
    float* out = (float*)d_out;

    void *pbqh, *pqkv, *pat, *pbph;
    void *px2, *pb1h, *ph, *pb2h, *px3, *pblh;
    cudaGetSymbolAddress(&pbqh, g_bqkvh);
    cudaGetSymbolAddress(&pqkv, g_qkv);
    cudaGetSymbolAddress(&pat, g_att);
    cudaGetSymbolAddress(&pbph, g_bprojh);
    cudaGetSymbolAddress(&px2, g_x2);
    cudaGetSymbolAddress(&pb1h, g_b1h);
    cudaGetSymbolAddress(&ph, g_h);
    cudaGetSymbolAddress(&pb2h, g_b2h);
    cudaGetSymbolAddress(&px3, g_x3);
    cudaGetSymbolAddress(&pblh, g_blmh);

    const int SMEM = NSTAGE * STAGE_B;  // 98304
    cudaFuncSetAttribute(tc_gemm<false,false,false,false,true >, cudaFuncAttributeMaxDynamicSharedMemorySize, SMEM);
    cudaFuncSetAttribute(tc_gemm<false,true, true, false,false>, cudaFuncAttributeMaxDynamicSharedMemorySize, SMEM);
    cudaFuncSetAttribute(tc_gemm<true, true, true, false,false>, cudaFuncAttributeMaxDynamicSharedMemorySize, SMEM);
    cudaFuncSetAttribute(tc_gemm<false,true, false,true, false>, cudaFuncAttributeMaxDynamicSharedMemorySize, SMEM);

    pack_weights<<<(PACKT + 255)/256, 256>>>(Wq, Wk, Wv, Wproj, W1, W2, Wlm);   // L1

    // qkv (embed fused): gather-A [BT,384] @ [384,72pad128] -> float g_qkv     // L2
    tc_gemm<false,false,false,false,true><<<dim3(1, BTn/128), 256, SMEM>>>(
        nullptr, Cn, (const __half*)pbqh,
        nullptr, (float*)pqkv, 72, 72, nullptr, 0, nullptr, idx, tok, pos);

    attn_kernel<<<128 * Hn, 256>>>();                                           // L3

    // proj: [BT,64pad] @ [64,384] + bproj -> fp16 x2                           // L4
    tc_gemm<false,true,true,false,false><<<dim3(3, BTn/128), 256, SMEM>>>(
        (const __half*)pat, 64, (const __half*)pbph,
        bproj, nullptr, 0, 0, (__half*)px2, Cn, nullptr, nullptr, nullptr, nullptr);

    // ffn1: relu([BT,384] @ [384,1536] + b1) -> fp16 h
    tc_gemm<true,true,true,false,false><<<dim3(12, BTn/128), 256, SMEM>>>(
        (const __half*)px2, Cn, (const __half*)pb1h,
        b1, nullptr, 0, 0, (__half*)ph, Fn, nullptr, nullptr, nullptr, nullptr);

    // ffn2: [BT,1536] @ [1536,384] + b2 -> fp16 x3
    tc_gemm<false,true,true,false,false><<<dim3(3, BTn/128), 256, SMEM>>>(
        (const __half*)ph, Fn, (const __half*)pb2h,
        b2, nullptr, 0, 0, (__half*)px3, Cn, nullptr, nullptr, nullptr, nullptr);

    // lm: [BT,384] @ [384,65pad128] + blm -> logits + fused rowloss
    tc_gemm<false,true,false,true,false><<<dim3(1, BTn/128), 256, SMEM>>>(
        (const __half*)px3, Cn, (const __half*)pblh,
        blm, out, Vn, Vn, nullptr, 0, targets, nullptr, nullptr, nullptr);

    loss_reduce_kernel<<<1, 256>>>(out, out_size);
}